// round 7
// baseline (speedup 1.0000x reference)
#include <cuda_runtime.h>
#include <cuda_bf16.h>
#include <math.h>
#include <stdint.h>

#define BB 4
#define NN 1024
#define CC 1024
#define HH 16
#define DH 64
#define MROWS (BB*NN)   // 4096

// ---------------- scratch (device globals; no allocation allowed) ----------
__device__ float g_logits[BB*NN*NN];               // 16 MB
__device__ __nv_bfloat16 g_xh[MROWS*CC];
__device__ __nv_bfloat16 g_xl[MROWS*CC];
__device__ __nv_bfloat16 g_preh[MROWS*CC];
__device__ __nv_bfloat16 g_prel[MROWS*CC];
__device__ __nv_bfloat16 g_ctxh[MROWS*CC];
__device__ __nv_bfloat16 g_ctxl[MROWS*CC];
__device__ __nv_bfloat16 g_qh[BB*HH*NN*DH], g_ql[BB*HH*NN*DH];
__device__ __nv_bfloat16 g_kh[BB*HH*NN*DH], g_kl[BB*HH*NN*DH];
__device__ __nv_bfloat16 g_vh[BB*HH*NN*DH], g_vl[BB*HH*NN*DH];
__device__ __nv_bfloat16 g_wpreh[CC*CC], g_wprel[CC*CC];
__device__ __nv_bfloat16 g_wqh[CC*CC],  g_wql[CC*CC];
__device__ __nv_bfloat16 g_wkh[CC*CC],  g_wkl[CC*CC];
__device__ __nv_bfloat16 g_wvh[CC*CC],  g_wvl[CC*CC];
__device__ __nv_bfloat16 g_wph[CC*CC],  g_wpl[CC*CC];

// ======================= portable PTX helpers ==============================
__device__ __forceinline__ uint32_t smem_to_u32(const void* p) {
    uint32_t a;
    asm("{ .reg .u64 t; cvta.to.shared.u64 t, %1; cvt.u32.u64 %0, t; }"
        : "=r"(a) : "l"(p));
    return a;
}
#define CP_ASYNC16(dst, src) \
    asm volatile("cp.async.cg.shared.global [%0], [%1], 16;" \
                 :: "r"(dst), "l"(src) : "memory")
#define CP_COMMIT() asm volatile("cp.async.commit_group;" ::: "memory")
#define CP_WAIT2()  asm volatile("cp.async.wait_group 2;" ::: "memory")
#define CP_WAIT1()  asm volatile("cp.async.wait_group 1;" ::: "memory")
#define CP_WAIT0()  asm volatile("cp.async.wait_group 0;" ::: "memory")

__device__ __forceinline__ void ldsm4(uint32_t* r, uint32_t addr) {
    asm volatile("ldmatrix.sync.aligned.m8n8.x4.shared.b16 {%0,%1,%2,%3}, [%4];"
        : "=r"(r[0]), "=r"(r[1]), "=r"(r[2]), "=r"(r[3]) : "r"(addr));
}
__device__ __forceinline__ void ldsm4t(uint32_t* r, uint32_t addr) {
    asm volatile("ldmatrix.sync.aligned.m8n8.x4.trans.shared.b16 {%0,%1,%2,%3}, [%4];"
        : "=r"(r[0]), "=r"(r[1]), "=r"(r[2]), "=r"(r[3]) : "r"(addr));
}
__device__ __forceinline__ void mma16816(float* c, const uint32_t* a,
                                         const uint32_t* b) {
    asm volatile("mma.sync.aligned.m16n8k16.row.col.f32.bf16.bf16.f32 "
        "{%0,%1,%2,%3}, {%4,%5,%6,%7}, {%8,%9}, {%0,%1,%2,%3};"
        : "+f"(c[0]), "+f"(c[1]), "+f"(c[2]), "+f"(c[3])
        : "r"(a[0]), "r"(a[1]), "r"(a[2]), "r"(a[3]), "r"(b[0]), "r"(b[1]));
}
__device__ __forceinline__ uint32_t pack_bf16(float x, float y) {
    __nv_bfloat162 p = __halves2bfloat162(__float2bfloat16(x), __float2bfloat16(y));
    return *(uint32_t*)&p;
}

// ======================= prep kernels ======================================
__global__ __launch_bounds__(256) void split2(
    const float2* __restrict__ in, __nv_bfloat162* __restrict__ hi,
    __nv_bfloat162* __restrict__ lo, int n2)
{
    int i = blockIdx.x * blockDim.x + threadIdx.x;
    if (i < n2) {
        float2 a = in[i];
        __nv_bfloat16 hx = __float2bfloat16(a.x), hy = __float2bfloat16(a.y);
        float lx = a.x - __bfloat162float(hx), ly = a.y - __bfloat162float(hy);
        hi[i] = __halves2bfloat162(hx, hy);
        lo[i] = __halves2bfloat162(__float2bfloat16(lx), __float2bfloat16(ly));
    }
}

__global__ __launch_bounds__(256) void wsplit_T5(
    const float* __restrict__ W0, const float* __restrict__ W1,
    const float* __restrict__ W2, const float* __restrict__ W3,
    const float* __restrict__ W4,
    __nv_bfloat16* o0h, __nv_bfloat16* o0l, __nv_bfloat16* o1h, __nv_bfloat16* o1l,
    __nv_bfloat16* o2h, __nv_bfloat16* o2l, __nv_bfloat16* o3h, __nv_bfloat16* o3l,
    __nv_bfloat16* o4h, __nv_bfloat16* o4l)
{
    const float* Ws[5] = {W0, W1, W2, W3, W4};
    __nv_bfloat16* Hs[5] = {o0h, o1h, o2h, o3h, o4h};
    __nv_bfloat16* Ls[5] = {o0l, o1l, o2l, o3l, o4l};
    const int z = blockIdx.z;
    const float* W = Ws[z];
    __nv_bfloat16* th = Hs[z];
    __nv_bfloat16* tl = Ls[z];

    __shared__ float s[32][33];
    const int tx = threadIdx.x, ty = threadIdx.y;
    const int n0 = blockIdx.x * 32, k0 = blockIdx.y * 32;
#pragma unroll
    for (int i = ty; i < 32; i += 8)
        s[i][tx] = W[(size_t)(k0 + i) * CC + n0 + tx];
    __syncthreads();
#pragma unroll
    for (int i = ty; i < 32; i += 8) {
        float v = s[tx][i];
        __nv_bfloat16 h = __float2bfloat16(v);
        float l = v - __bfloat162float(h);
        size_t o = (size_t)(n0 + i) * CC + k0 + tx;
        th[o] = h; tl[o] = __float2bfloat16(l);
    }
}

// ======================= HMMA GEMM common machinery ========================
enum { EPI_PRE = 0, EPI_BHND = 1, EPI_LOGITS = 2, EPI_RESID = 3 };

#define OFF_AH 0
#define OFF_AL 8192
#define OFF_BH 16384
#define OFF_BL 24576
#define STAGE_BYTES 32768
#define NSTAGE 4
#define SMEM_HMMA (NSTAGE * STAGE_BYTES)    // 131072

struct GemmCore {
    uint32_t smem_u32;
    int lane, wid, wr, wc, lrow, lc, rowSel, hiH, rmod;
    __device__ __forceinline__ void init(uint32_t smem, int t) {
        smem_u32 = smem;
        lane = t & 31; wid = t >> 5;
        wr = wid & 1; wc = wid >> 1;
        lrow = t >> 2; lc = t & 3;
        rowSel = lane & 15; hiH = lane >> 4; rmod = rowSel & 3;
    }
    __device__ __forceinline__ void load_stage(
        const __nv_bfloat16* Ahb, const __nv_bfloat16* Alb,
        const __nv_bfloat16* Bhb, const __nv_bfloat16* Blb,
        int row0, int col0, int ch, int s) const
    {
        const size_t kb = (size_t)ch * 32 + lc * 8;
        const uint32_t sb = smem_u32 + s * STAGE_BYTES;
#pragma unroll
        for (int i = 0; i < 2; i++) {
            const int r = lrow + i * 64;
            const uint32_t so = (uint32_t)(r * 64 + ((lc ^ (r & 3)) * 16));
            const size_t ga = (size_t)(row0 + r) * CC + kb;
            const size_t gb = (size_t)(col0 + r) * CC + kb;
            CP_ASYNC16(sb + OFF_AH + so, Ahb + ga);
            CP_ASYNC16(sb + OFF_AL + so, Alb + ga);
            CP_ASYNC16(sb + OFF_BH + so, Bhb + gb);
            CP_ASYNC16(sb + OFF_BL + so, Blb + gb);
        }
    }
    __device__ __forceinline__ void run(
        const __nv_bfloat16* Ahb, const __nv_bfloat16* Alb,
        const __nv_bfloat16* Bhb, const __nv_bfloat16* Blb,
        int row0, int col0, float acc[4][4][4]) const
    {
#pragma unroll
        for (int a = 0; a < 4; a++)
#pragma unroll
            for (int b = 0; b < 4; b++)
#pragma unroll
                for (int c = 0; c < 4; c++) acc[a][b][c] = 0.0f;

        // prologue: stages 0..2 in flight (prefetch distance 3)
#pragma unroll
        for (int s = 0; s < 3; s++) {
            load_stage(Ahb, Alb, Bhb, Blb, row0, col0, s, s);
            CP_COMMIT();
        }
        for (int ch = 0; ch < 32; ch++) {
            if (ch < 30) CP_WAIT2();
            else if (ch == 30) CP_WAIT1();
            else CP_WAIT0();
            __syncthreads();   // stage ch visible; buffer (ch+3)%4 free to refill
            if (ch < 29) {
                load_stage(Ahb, Alb, Bhb, Blb, row0, col0, ch + 3, (ch + 3) & 3);
                CP_COMMIT();
            }

            const uint32_t sb = smem_u32 + (ch & 3) * STAGE_BYTES;
#pragma unroll
            for (int k16 = 0; k16 < 2; k16++) {
                const int chunk = k16 * 2 + hiH;
                uint32_t ah[4][4], al[4][4];
#pragma unroll
                for (int mt = 0; mt < 4; mt++) {
                    const int row = wr * 64 + mt * 16 + rowSel;
                    const uint32_t off = (uint32_t)(row * 64 + ((chunk ^ rmod) * 16));
                    ldsm4(ah[mt], sb + OFF_AH + off);
                    ldsm4(al[mt], sb + OFF_AL + off);
                }
                uint32_t bh[4][2], bl[4][2];
#pragma unroll
                for (int n16 = 0; n16 < 2; n16++) {
                    const int row = wc * 32 + n16 * 16 + rowSel;
                    const uint32_t off = (uint32_t)(row * 64 + ((chunk ^ rmod) * 16));
                    uint32_t rh[4], rl[4];
                    ldsm4(rh, sb + OFF_BH + off);
                    ldsm4(rl, sb + OFF_BL + off);
                    bh[n16 * 2][0] = rh[0]; bh[n16 * 2 + 1][0] = rh[1];
                    bh[n16 * 2][1] = rh[2]; bh[n16 * 2 + 1][1] = rh[3];
                    bl[n16 * 2][0] = rl[0]; bl[n16 * 2 + 1][0] = rl[1];
                    bl[n16 * 2][1] = rl[2]; bl[n16 * 2 + 1][1] = rl[3];
                }
#pragma unroll
                for (int mt = 0; mt < 4; mt++)
#pragma unroll
                    for (int nt = 0; nt < 4; nt++) {
                        mma16816(acc[mt][nt], ah[mt], bh[nt]);
                        mma16816(acc[mt][nt], ah[mt], bl[nt]);
                        mma16816(acc[mt][nt], al[mt], bh[nt]);
                    }
            }
        }
        __syncthreads();
    }
};

__device__ __forceinline__ void split_store(__nv_bfloat16* oh, __nv_bfloat16* ol,
                                            size_t off, float v0, float v1) {
    __nv_bfloat16 h0 = __float2bfloat16(v0);
    __nv_bfloat16 h1 = __float2bfloat16(v1);
    *(__nv_bfloat162*)(oh + off) = __halves2bfloat162(h0, h1);
    *(__nv_bfloat162*)(ol + off) = __halves2bfloat162(
        __float2bfloat16(v0 - __bfloat162float(h0)),
        __float2bfloat16(v1 - __bfloat162float(h1)));
}

// ---- merged pre/Q/K/V GEMM ------------------------------------------------
__global__ __launch_bounds__(256) void hmma_qkv(
    const __nv_bfloat16* __restrict__ xh, const __nv_bfloat16* __restrict__ xl,
    const __nv_bfloat16* wpreh, const __nv_bfloat16* wprel,
    const __nv_bfloat16* wqh, const __nv_bfloat16* wql,
    const __nv_bfloat16* wkh, const __nv_bfloat16* wkl,
    const __nv_bfloat16* wvh, const __nv_bfloat16* wvl,
    const float* __restrict__ bpre,
    __nv_bfloat16* preh, __nv_bfloat16* prel,
    __nv_bfloat16* qh, __nv_bfloat16* ql,
    __nv_bfloat16* kh, __nv_bfloat16* kl,
    __nv_bfloat16* vh, __nv_bfloat16* vl)
{
    extern __shared__ char smem_raw[];
    GemmCore gc_;
    gc_.init(smem_to_u32(smem_raw), threadIdx.x);

    const int g    = blockIdx.x >> 3;
    const int col0 = (blockIdx.x & 7) * 128;
    const int row0 = blockIdx.y * 128;

    const __nv_bfloat16* Bh[4] = {wpreh, wqh, wkh, wvh};
    const __nv_bfloat16* Bl[4] = {wprel, wql, wkl, wvl};
    __nv_bfloat16* OH[4] = {preh, qh, kh, vh};
    __nv_bfloat16* OL[4] = {prel, ql, kl, vl};

    float acc[4][4][4];
    gc_.run(xh, xl, Bh[g], Bl[g], row0, col0, acc);

    const int r0g = row0 + gc_.wr * 64 + (gc_.lane >> 2);
    const int c0g = col0 + gc_.wc * 32 + (gc_.lane & 3) * 2;
#pragma unroll
    for (int mt = 0; mt < 4; mt++) {
#pragma unroll
        for (int nt = 0; nt < 4; nt++) {
            const int gcc = c0g + nt * 8;
#pragma unroll
            for (int half = 0; half < 2; half++) {
                const int gr = r0g + mt * 16 + half * 8;
                float v0 = acc[mt][nt][half * 2 + 0];
                float v1 = acc[mt][nt][half * 2 + 1];
                if (g == 0) {
                    v0 += bpre[gcc]; v1 += bpre[gcc + 1];
                    v0 = v0 / (1.0f + __expf(-v0));
                    v1 = v1 / (1.0f + __expf(-v1));
                    split_store(OH[0], OL[0], (size_t)gr * CC + gcc, v0, v1);
                } else {
                    const int b = gr >> 10, n = gr & (NN - 1);
                    const int h = gcc >> 6, dh = gcc & 63;
                    const size_t o = ((size_t)(b * HH + h) * NN + n) * DH + dh;
                    split_store(OH[g], OL[g], o, v0, v1);
                }
            }
        }
    }
}

// ---- logits (symmetric, upper-tri tiles) + proj/resid GEMM ----------------
__global__ __launch_bounds__(256) void hmma_gemm(
    const __nv_bfloat16* __restrict__ Ah, const __nv_bfloat16* __restrict__ Al,
    const __nv_bfloat16* __restrict__ Bh, const __nv_bfloat16* __restrict__ Bl,
    const float* __restrict__ bias, const float* __restrict__ resid,
    float* __restrict__ outF, int mode, long long bsA, long long bsB)
{
    extern __shared__ char smem_raw[];
    GemmCore gc_;
    gc_.init(smem_to_u32(smem_raw), threadIdx.x);

    int row0, col0, ti = 0, tj = 0;
    if (mode == EPI_LOGITS) {
        int li = blockIdx.x, rem = 8;
        while (li >= rem) { li -= rem; rem--; ti++; }
        tj = ti + li;
        row0 = ti * 128; col0 = tj * 128;
    } else {
        row0 = blockIdx.y * 128;
        col0 = blockIdx.x * 128;
    }
    const int z = blockIdx.z;
    const __nv_bfloat16* Ahb = Ah + (size_t)z * bsA;
    const __nv_bfloat16* Alb = Al + (size_t)z * bsA;
    const __nv_bfloat16* Bhb = Bh + (size_t)z * bsB;
    const __nv_bfloat16* Blb = Bl + (size_t)z * bsB;

    float acc[4][4][4];
    gc_.run(Ahb, Alb, Bhb, Blb, row0, col0, acc);

    const int r0g = row0 + gc_.wr * 64 + (gc_.lane >> 2);
    const int c0g = col0 + gc_.wc * 32 + (gc_.lane & 3) * 2;
#pragma unroll
    for (int mt = 0; mt < 4; mt++) {
#pragma unroll
        for (int nt = 0; nt < 4; nt++) {
            const int gcc = c0g + nt * 8;
#pragma unroll
            for (int half = 0; half < 2; half++) {
                const int gr = r0g + mt * 16 + half * 8;
                float v0 = acc[mt][nt][half * 2 + 0];
                float v1 = acc[mt][nt][half * 2 + 1];
                if (mode == EPI_LOGITS) {
                    float* base = outF + (size_t)z * NN * NN;
                    v0 *= 0.03125f; v1 *= 0.03125f;
                    base[(size_t)gr * NN + gcc]     = v0;
                    base[(size_t)gr * NN + gcc + 1] = v1;
                    if (ti != tj) {
                        base[(size_t)gcc * NN + gr]       = v0;
                        base[(size_t)(gcc + 1) * NN + gr] = v1;
                    }
                } else { // EPI_RESID
                    const size_t ro = (size_t)gr * CC + gcc;
                    outF[ro]     = v0 + bias[gcc]     + resid[ro];
                    outF[ro + 1] = v1 + bias[gcc + 1] + resid[ro + 1];
                }
            }
        }
    }
}

// ======================= HMMA flash attention (128-q tile) =================
// Q resident (32KB) + double-buffered K/V stages (2 x 32KB).
#define SMQ_H 0
#define SMQ_L 16384
#define KVST 32768
#define KV_KH 0
#define KV_KL 8192
#define KV_VH 16384
#define KV_VL 24576
#define SMEM_FATT (32768 + 2 * KVST)    // 98304

__global__ __launch_bounds__(256, 2) void fattn(
    const __nv_bfloat16* __restrict__ qh, const __nv_bfloat16* __restrict__ ql,
    const __nv_bfloat16* __restrict__ kh, const __nv_bfloat16* __restrict__ kl,
    const __nv_bfloat16* __restrict__ vh, const __nv_bfloat16* __restrict__ vl,
    const float* __restrict__ logits, const float* __restrict__ pi_p,
    __nv_bfloat16* __restrict__ ctxh, __nv_bfloat16* __restrict__ ctxl)
{
    extern __shared__ char sm[];
    const uint32_t sb = smem_to_u32(sm);
    const int t = threadIdx.x, lane = t & 31, w = t >> 5;
    const int bh = blockIdx.y, b = bh >> 4, h = bh & 15;
    const int q0 = blockIdx.x * 128;
    const size_t hoff = (size_t)bh * NN * DH;
    const float pi = pi_p[0];

    // Q async load (once)
#pragma unroll
    for (int i = 0; i < 4; i++) {
        const int id = t + i * 256;
        const int r = id >> 3, c = id & 7;
        const uint32_t off = (uint32_t)(r * 128 + ((c ^ (r & 7)) * 16));
        const size_t g = hoff + (size_t)(q0 + r) * DH + c * 8;
        CP_ASYNC16(sb + SMQ_H + off, qh + g);
        CP_ASYNC16(sb + SMQ_L + off, ql + g);
    }
    CP_COMMIT();

    auto load_kv = [&](int kt, int buf) {
        const uint32_t kvb = sb + 32768 + buf * KVST;
#pragma unroll
        for (int i = 0; i < 2; i++) {
            const int id = t + i * 256;
            const int r = id >> 3, c = id & 7;
            const uint32_t off = (uint32_t)(r * 128 + ((c ^ (r & 7)) * 16));
            const size_t g = hoff + (size_t)(kt * 64 + r) * DH + c * 8;
            CP_ASYNC16(kvb + KV_KH + off, kh + g);
            CP_ASYNC16(kvb + KV_KL + off, kl + g);
            CP_ASYNC16(kvb + KV_VH + off, vh + g);
            CP_ASYNC16(kvb + KV_VL + off, vl + g);
        }
    };

    load_kv(0, 0);
    CP_COMMIT();

    float S[8][4], O[8][4];
#pragma unroll
    for (int j = 0; j < 8; j++)
#pragma unroll
        for (int c = 0; c < 4; c++) O[j][c] = 0.0f;
    float m0 = -1e30f, m1 = -1e30f, l0 = 0.0f, l1 = 0.0f;

    const int qr = w * 16 + (lane >> 2);
    const float* lgr = logits + (size_t)b * NN * NN + (size_t)(q0 + qr) * NN;
    const int rowSel = lane & 15, hiH = lane >> 4;

    for (int kt = 0; kt < 16; kt++) {
        const int mk = kt * 64;
        __syncthreads();            // all warps done reading buf (kt+1)&1 (iter kt-1)
        if (kt < 15) { load_kv(kt + 1, (kt + 1) & 1); CP_COMMIT(); CP_WAIT1(); }
        else CP_WAIT0();
        __syncthreads();            // tile kt visible to all warps

        const uint32_t kvb = sb + 32768 + (kt & 1) * KVST;

        // ---- S = Q K^T (3-term) ----
#pragma unroll
        for (int j = 0; j < 8; j++)
#pragma unroll
            for (int c = 0; c < 4; c++) S[j][c] = 0.0f;

#pragma unroll
        for (int kc = 0; kc < 4; kc++) {
            const int chunk = 2 * kc + hiH;
            uint32_t aqh[4], aql[4];
            {
                const int row = w * 16 + rowSel;
                const uint32_t off = (uint32_t)(row * 128 + ((chunk ^ (row & 7)) * 16));
                ldsm4(aqh, sb + SMQ_H + off);
                ldsm4(aql, sb + SMQ_L + off);
            }
#pragma unroll
            for (int j16 = 0; j16 < 4; j16++) {
                const int row = j16 * 16 + rowSel;
                const uint32_t off = (uint32_t)(row * 128 + ((chunk ^ (row & 7)) * 16));
                uint32_t rh[4], rl[4];
                ldsm4(rh, kvb + KV_KH + off);
                ldsm4(rl, kvb + KV_KL + off);
                uint32_t b0h[2] = {rh[0], rh[2]}, b1h[2] = {rh[1], rh[3]};
                uint32_t b0l[2] = {rl[0], rl[2]}, b1l[2] = {rl[1], rl[3]};
                mma16816(S[2 * j16],     aqh, b0h);
                mma16816(S[2 * j16],     aqh, b0l);
                mma16816(S[2 * j16],     aql, b0h);
                mma16816(S[2 * j16 + 1], aqh, b1h);
                mma16816(S[2 * j16 + 1], aqh, b1l);
                mma16816(S[2 * j16 + 1], aql, b1h);
            }
        }

        // ---- bias + online softmax ----
        float mx0 = -1e30f, mx1 = -1e30f;
#pragma unroll
        for (int j = 0; j < 8; j++) {
            const float2 L0 = *(const float2*)(lgr + mk + j * 8 + (lane & 3) * 2);
            const float2 L1 = *(const float2*)(lgr + 8 * NN + mk + j * 8 + (lane & 3) * 2);
            S[j][0] = S[j][0] * 0.125f + pi * L0.x;
            S[j][1] = S[j][1] * 0.125f + pi * L0.y;
            S[j][2] = S[j][2] * 0.125f + pi * L1.x;
            S[j][3] = S[j][3] * 0.125f + pi * L1.y;
            mx0 = fmaxf(mx0, fmaxf(S[j][0], S[j][1]));
            mx1 = fmaxf(mx1, fmaxf(S[j][2], S[j][3]));
        }
        mx0 = fmaxf(mx0, __shfl_xor_sync(0xffffffffu, mx0, 1));
        mx0 = fmaxf(mx0, __shfl_xor_sync(0xffffffffu, mx0, 2));
        mx1 = fmaxf(mx1, __shfl_xor_sync(0xffffffffu, mx1, 1));
        mx1 = fmaxf(mx1, __shfl_xor_sync(0xffffffffu, mx1, 2));
        const float mn0 = fmaxf(m0, mx0), mn1 = fmaxf(m1, mx1);
        const float a0 = __expf(m0 - mn0), a1 = __expf(m1 - mn1);
        m0 = mn0; m1 = mn1;
        float s0 = 0.0f, s1 = 0.0f;
#pragma unroll
        for (int j = 0; j < 8; j++) {
            S[j][0] = __expf(S[j][0] - mn0); S[j][1] = __expf(S[j][1] - mn0);
            S[j][2] = __expf(S[j][2] - mn1); S[j][3] = __expf(S[j][3] - mn1);
            s0 += S[j][0] + S[j][1];
            s1 += S[j][2] + S[j][3];
        }
        s0 += __shfl_xor_sync(0xffffffffu, s0, 1);
        s0 += __shfl_xor_sync(0xffffffffu, s0, 2);
        s1 += __shfl_xor_sync(0xffffffffu, s1, 1);
        s1 += __shfl_xor_sync(0xffffffffu, s1, 2);
        l0 = l0 * a0 + s0; l1 = l1 * a1 + s1;
#pragma unroll
        for (int j = 0; j < 8; j++) {
            O[j][0] *= a0; O[j][1] *= a0; O[j][2] *= a1; O[j][3] *= a1;
        }

        // ---- O += P V (3-term) ----
#pragma unroll
        for (int kc = 0; kc < 4; kc++) {
            uint32_t ph[4], pl[4];
#pragma unroll
            for (int half = 0; half < 2; half++) {
                const int j = 2 * kc + half;
                float x0 = S[j][0], x1 = S[j][1], x2 = S[j][2], x3 = S[j][3];
                uint32_t hp = pack_bf16(x0, x1);
                uint32_t hq = pack_bf16(x2, x3);
                ph[half * 2 + 0] = hp;
                ph[half * 2 + 1] = hq;
                __nv_bfloat162 hp2 = *(__nv_bfloat162*)&hp;
                __nv_bfloat162 hq2 = *(__nv_bfloat162*)&hq;
                pl[half * 2 + 0] = pack_bf16(x0 - __bfloat162float(__low2bfloat16(hp2)),
                                             x1 - __bfloat162float(__high2bfloat16(hp2)));
                pl[half * 2 + 1] = pack_bf16(x2 - __bfloat162float(__low2bfloat16(hq2)),
                                             x3 - __bfloat162float(__high2bfloat16(hq2)));
            }
#pragma unroll
            for (int jc = 0; jc < 4; jc++) {
                const int row = kc * 16 + rowSel;
                const int chunk = 2 * jc + hiH;
                const uint32_t off = (uint32_t)(row * 128 + ((chunk ^ (row & 7)) * 16));
                uint32_t rvh[4], rvl[4];
                ldsm4t(rvh, kvb + KV_VH + off);
                ldsm4t(rvl, kvb + KV_VL + off);
                uint32_t v0h[2] = {rvh[0], rvh[1]}, v1h[2] = {rvh[2], rvh[3]};
                uint32_t v0l[2] = {rvl[0], rvl[1]}, v1l[2] = {rvl[2], rvl[3]};
                mma16816(O[2 * jc],     ph, v0h);
                mma16816(O[2 * jc],     ph, v0l);
                mma16816(O[2 * jc],     pl, v0h);
                mma16816(O[2 * jc + 1], ph, v1h);
                mma16816(O[2 * jc + 1], ph, v1l);
                mma16816(O[2 * jc + 1], pl, v1h);
            }
        }
    }

    // ---- epilogue ----
    const float inv0 = 1.0f / l0, inv1 = 1.0f / l1;
    const size_t r0o = (size_t)(b * NN + q0 + qr) * CC;
    const size_t r1o = r0o + (size_t)8 * CC;
    const int cb = h * DH + (lane & 3) * 2;
#pragma unroll
    for (int dj = 0; dj < 8; dj++) {
        const int col = cb + dj * 8;
        split_store(ctxh, ctxl, r0o + col, O[dj][0] * inv0, O[dj][1] * inv0);
        split_store(ctxh, ctxl, r1o + col, O[dj][2] * inv1, O[dj][3] * inv1);
    }
}

// ---------------------------------------------------------------------------
extern "C" void kernel_launch(void* const* d_in, const int* in_sizes, int n_in,
                              void* d_out, int out_size)
{
    (void)in_sizes; (void)n_in; (void)out_size;
    const float* x     = (const float*)d_in[0];
    const float* Wq    = (const float*)d_in[1];
    const float* Wk    = (const float*)d_in[2];
    const float* Wv    = (const float*)d_in[3];
    const float* Wproj = (const float*)d_in[4];
    const float* bproj = (const float*)d_in[5];
    const float* Wpre  = (const float*)d_in[6];
    const float* bpre  = (const float*)d_in[7];
    const float* pi    = (const float*)d_in[8];
    float* out = (float*)d_out;

    float* lgp;
    __nv_bfloat16 *xh, *xl, *preh, *prel, *ctxh, *ctxl;
    __nv_bfloat16 *qhp, *qlp, *khp, *klp, *vhp, *vlp;
    __nv_bfloat16 *wpreh, *wprel, *wqh, *wql, *wkh, *wkl, *wvh, *wvl, *wph, *wpl;
    cudaGetSymbolAddress((void**)&lgp,   g_logits);
    cudaGetSymbolAddress((void**)&xh,    g_xh);
    cudaGetSymbolAddress((void**)&xl,    g_xl);
    cudaGetSymbolAddress((void**)&preh,  g_preh);
    cudaGetSymbolAddress((void**)&prel,  g_prel);
    cudaGetSymbolAddress((void**)&ctxh,  g_ctxh);
    cudaGetSymbolAddress((void**)&ctxl,  g_ctxl);
    cudaGetSymbolAddress((void**)&qhp,   g_qh);
    cudaGetSymbolAddress((void**)&qlp,   g_ql);
    cudaGetSymbolAddress((void**)&khp,   g_kh);
    cudaGetSymbolAddress((void**)&klp,   g_kl);
    cudaGetSymbolAddress((void**)&vhp,   g_vh);
    cudaGetSymbolAddress((void**)&vlp,   g_vl);
    cudaGetSymbolAddress((void**)&wpreh, g_wpreh);
    cudaGetSymbolAddress((void**)&wprel, g_wprel);
    cudaGetSymbolAddress((void**)&wqh,   g_wqh);
    cudaGetSymbolAddress((void**)&wql,   g_wql);
    cudaGetSymbolAddress((void**)&wkh,   g_wkh);
    cudaGetSymbolAddress((void**)&wkl,   g_wkl);
    cudaGetSymbolAddress((void**)&wvh,   g_wvh);
    cudaGetSymbolAddress((void**)&wvl,   g_wvl);
    cudaGetSymbolAddress((void**)&wph,   g_wph);
    cudaGetSymbolAddress((void**)&wpl,   g_wpl);

    cudaFuncSetAttribute(hmma_qkv,  cudaFuncAttributeMaxDynamicSharedMemorySize, SMEM_HMMA);
    cudaFuncSetAttribute(hmma_gemm, cudaFuncAttributeMaxDynamicSharedMemorySize, SMEM_HMMA);
    cudaFuncSetAttribute(fattn,     cudaFuncAttributeMaxDynamicSharedMemorySize, SMEM_FATT);

    // ---- prep ----
    dim3 wst(32, 8), wsg(32, 32, 5);
    wsplit_T5<<<wsg, wst>>>(Wpre, Wq, Wk, Wv, Wproj,
                            wpreh, wprel, wqh, wql, wkh, wkl, wvh, wvl, wph, wpl);
    const int n2 = MROWS * CC / 2;
    split2<<<(n2 + 255) / 256, 256>>>((const float2*)x,
        (__nv_bfloat162*)xh, (__nv_bfloat162*)xl, n2);

    // ---- merged pre/Q/K/V GEMM ----
    dim3 mb(256);
    dim3 gqkv(32, MROWS / 128, 1);
    hmma_qkv<<<gqkv, mb, SMEM_HMMA>>>(xh, xl,
        wpreh, wprel, wqh, wql, wkh, wkl, wvh, wvl, bpre,
        preh, prel, qhp, qlp, khp, klp, vhp, vlp);

    // ---- logits GEMM (symmetric: 36 upper-tri tiles/batch) ----
    dim3 glog(36, 1, BB);
    hmma_gemm<<<glog, mb, SMEM_HMMA>>>(preh, prel, preh, prel, nullptr, nullptr,
                                       lgp, EPI_LOGITS,
                                       (long long)NN * CC, (long long)NN * CC);

    // ---- HMMA flash attention ----
    dim3 ga(NN / 128, BB * HH);
    fattn<<<ga, 256, SMEM_FATT>>>(qhp, qlp, khp, klp, vhp, vlp, lgp, pi,
                                  ctxh, ctxl);

    // ---- projection + residual ----
    dim3 gl(CC / 128, MROWS / 128, 1);
    hmma_gemm<<<gl, mb, SMEM_HMMA>>>(ctxh, ctxl, wph, wpl, bproj, x,
                                     out, EPI_RESID, 0, 0);
}

// round 8
// speedup vs baseline: 1.1558x; 1.1558x over previous
#include <cuda_runtime.h>
#include <cuda_bf16.h>
#include <math.h>
#include <stdint.h>

#define BB 4
#define NN 1024
#define CC 1024
#define HH 16
#define DH 64
#define MROWS (BB*NN)   // 4096

// ---------------- scratch (device globals; no allocation allowed) ----------
__device__ float g_logits[BB*NN*NN];               // 16 MB
__device__ __nv_bfloat16 g_xh[MROWS*CC];
__device__ __nv_bfloat16 g_xl[MROWS*CC];
__device__ __nv_bfloat16 g_preh[MROWS*CC];
__device__ __nv_bfloat16 g_prel[MROWS*CC];
__device__ __nv_bfloat16 g_ctxh[MROWS*CC];
__device__ __nv_bfloat16 g_ctxl[MROWS*CC];
__device__ __nv_bfloat16 g_qh[BB*HH*NN*DH], g_ql[BB*HH*NN*DH];
__device__ __nv_bfloat16 g_kh[BB*HH*NN*DH], g_kl[BB*HH*NN*DH];
__device__ __nv_bfloat16 g_vh[BB*HH*NN*DH], g_vl[BB*HH*NN*DH];
__device__ __nv_bfloat16 g_wpreh[CC*CC], g_wprel[CC*CC];
__device__ __nv_bfloat16 g_wqh[CC*CC],  g_wql[CC*CC];
__device__ __nv_bfloat16 g_wkh[CC*CC],  g_wkl[CC*CC];
__device__ __nv_bfloat16 g_wvh[CC*CC],  g_wvl[CC*CC];
__device__ __nv_bfloat16 g_wph[CC*CC],  g_wpl[CC*CC];

// ======================= portable PTX helpers ==============================
__device__ __forceinline__ uint32_t smem_to_u32(const void* p) {
    uint32_t a;
    asm("{ .reg .u64 t; cvta.to.shared.u64 t, %1; cvt.u32.u64 %0, t; }"
        : "=r"(a) : "l"(p));
    return a;
}
#define CP_ASYNC16(dst, src) \
    asm volatile("cp.async.cg.shared.global [%0], [%1], 16;" \
                 :: "r"(dst), "l"(src) : "memory")
#define CP_COMMIT() asm volatile("cp.async.commit_group;" ::: "memory")
#define CP_WAIT1()  asm volatile("cp.async.wait_group 1;" ::: "memory")
#define CP_WAIT0()  asm volatile("cp.async.wait_group 0;" ::: "memory")

__device__ __forceinline__ void ldsm4(uint32_t* r, uint32_t addr) {
    asm volatile("ldmatrix.sync.aligned.m8n8.x4.shared.b16 {%0,%1,%2,%3}, [%4];"
        : "=r"(r[0]), "=r"(r[1]), "=r"(r[2]), "=r"(r[3]) : "r"(addr));
}
__device__ __forceinline__ void ldsm4t(uint32_t* r, uint32_t addr) {
    asm volatile("ldmatrix.sync.aligned.m8n8.x4.trans.shared.b16 {%0,%1,%2,%3}, [%4];"
        : "=r"(r[0]), "=r"(r[1]), "=r"(r[2]), "=r"(r[3]) : "r"(addr));
}
__device__ __forceinline__ void mma16816(float* c, const uint32_t* a,
                                         const uint32_t* b) {
    asm volatile("mma.sync.aligned.m16n8k16.row.col.f32.bf16.bf16.f32 "
        "{%0,%1,%2,%3}, {%4,%5,%6,%7}, {%8,%9}, {%0,%1,%2,%3};"
        : "+f"(c[0]), "+f"(c[1]), "+f"(c[2]), "+f"(c[3])
        : "r"(a[0]), "r"(a[1]), "r"(a[2]), "r"(a[3]), "r"(b[0]), "r"(b[1]));
}
__device__ __forceinline__ uint32_t pack_bf16(float x, float y) {
    __nv_bfloat162 p = __halves2bfloat162(__float2bfloat16(x), __float2bfloat16(y));
    return *(uint32_t*)&p;
}

// ======================= prep kernels ======================================
__global__ __launch_bounds__(256) void split2(
    const float2* __restrict__ in, __nv_bfloat162* __restrict__ hi,
    __nv_bfloat162* __restrict__ lo, int n2)
{
    int i = blockIdx.x * blockDim.x + threadIdx.x;
    if (i < n2) {
        float2 a = in[i];
        __nv_bfloat16 hx = __float2bfloat16(a.x), hy = __float2bfloat16(a.y);
        float lx = a.x - __bfloat162float(hx), ly = a.y - __bfloat162float(hy);
        hi[i] = __halves2bfloat162(hx, hy);
        lo[i] = __halves2bfloat162(__float2bfloat16(lx), __float2bfloat16(ly));
    }
}

__global__ __launch_bounds__(256) void wsplit_T5(
    const float* __restrict__ W0, const float* __restrict__ W1,
    const float* __restrict__ W2, const float* __restrict__ W3,
    const float* __restrict__ W4,
    __nv_bfloat16* o0h, __nv_bfloat16* o0l, __nv_bfloat16* o1h, __nv_bfloat16* o1l,
    __nv_bfloat16* o2h, __nv_bfloat16* o2l, __nv_bfloat16* o3h, __nv_bfloat16* o3l,
    __nv_bfloat16* o4h, __nv_bfloat16* o4l)
{
    const float* Ws[5] = {W0, W1, W2, W3, W4};
    __nv_bfloat16* Hs[5] = {o0h, o1h, o2h, o3h, o4h};
    __nv_bfloat16* Ls[5] = {o0l, o1l, o2l, o3l, o4l};
    const int z = blockIdx.z;
    const float* W = Ws[z];
    __nv_bfloat16* th = Hs[z];
    __nv_bfloat16* tl = Ls[z];

    __shared__ float s[32][33];
    const int tx = threadIdx.x, ty = threadIdx.y;
    const int n0 = blockIdx.x * 32, k0 = blockIdx.y * 32;
#pragma unroll
    for (int i = ty; i < 32; i += 8)
        s[i][tx] = W[(size_t)(k0 + i) * CC + n0 + tx];
    __syncthreads();
#pragma unroll
    for (int i = ty; i < 32; i += 8) {
        float v = s[tx][i];
        __nv_bfloat16 h = __float2bfloat16(v);
        float l = v - __bfloat162float(h);
        size_t o = (size_t)(n0 + i) * CC + k0 + tx;
        th[o] = h; tl[o] = __float2bfloat16(l);
    }
}

// ======================= HMMA GEMM common machinery ========================
enum { EPI_PRE = 0, EPI_BHND = 1, EPI_LOGITS = 2, EPI_RESID = 3 };

#define OFF_AH 0
#define OFF_AL 8192
#define OFF_BH 16384
#define OFF_BL 24576
#define STAGE_BYTES 32768
#define SMEM_HMMA (2 * STAGE_BYTES)    // 65536

// Swizzle key: rows are 64B; bank-row is 128B (2 smem rows). Within an 8-row
// ldmatrix phase, even rows hit the low 64B half and odd rows the high half;
// key ((r>>1)&3) gives the 4 even (and 4 odd) rows distinct 16B chunks ->
// conflict-free. (Old key (r&3) collided rows r and r+4: 2-way conflict.)
struct GemmCore {
    uint32_t smem_u32;
    int lane, wid, wr, wc, lrow, lc, rowSel, hiH, rmod;
    __device__ __forceinline__ void init(uint32_t smem, int t) {
        smem_u32 = smem;
        lane = t & 31; wid = t >> 5;
        wr = wid & 1; wc = wid >> 1;
        lrow = t >> 2; lc = t & 3;
        rowSel = lane & 15; hiH = lane >> 4; rmod = (rowSel >> 1) & 3;
    }
    __device__ __forceinline__ void load_stage(
        const __nv_bfloat16* Ahb, const __nv_bfloat16* Alb,
        const __nv_bfloat16* Bhb, const __nv_bfloat16* Blb,
        int row0, int col0, int ch, int s) const
    {
        const size_t kb = (size_t)ch * 32 + lc * 8;
        const uint32_t sb = smem_u32 + s * STAGE_BYTES;
#pragma unroll
        for (int i = 0; i < 2; i++) {
            const int r = lrow + i * 64;
            const uint32_t so = (uint32_t)(r * 64 + ((lc ^ ((r >> 1) & 3)) * 16));
            const size_t ga = (size_t)(row0 + r) * CC + kb;
            const size_t gb = (size_t)(col0 + r) * CC + kb;
            CP_ASYNC16(sb + OFF_AH + so, Ahb + ga);
            CP_ASYNC16(sb + OFF_AL + so, Alb + ga);
            CP_ASYNC16(sb + OFF_BH + so, Bhb + gb);
            CP_ASYNC16(sb + OFF_BL + so, Blb + gb);
        }
    }
    __device__ __forceinline__ void run(
        const __nv_bfloat16* Ahb, const __nv_bfloat16* Alb,
        const __nv_bfloat16* Bhb, const __nv_bfloat16* Blb,
        int row0, int col0, float acc[4][4][4]) const
    {
#pragma unroll
        for (int a = 0; a < 4; a++)
#pragma unroll
            for (int b = 0; b < 4; b++)
#pragma unroll
                for (int c = 0; c < 4; c++) acc[a][b][c] = 0.0f;

        load_stage(Ahb, Alb, Bhb, Blb, row0, col0, 0, 0);
        CP_COMMIT();
        for (int ch = 0; ch < 32; ch++) {
            if (ch < 31) {
                load_stage(Ahb, Alb, Bhb, Blb, row0, col0, ch + 1, (ch + 1) & 1);
                CP_COMMIT(); CP_WAIT1();
            } else CP_WAIT0();
            __syncthreads();

            const uint32_t sb = smem_u32 + (ch & 1) * STAGE_BYTES;
#pragma unroll
            for (int k16 = 0; k16 < 2; k16++) {
                const int chunk = k16 * 2 + hiH;
                uint32_t ah[4][4], al[4][4];
#pragma unroll
                for (int mt = 0; mt < 4; mt++) {
                    const int row = wr * 64 + mt * 16 + rowSel;
                    const uint32_t off = (uint32_t)(row * 64 + ((chunk ^ rmod) * 16));
                    ldsm4(ah[mt], sb + OFF_AH + off);
                    ldsm4(al[mt], sb + OFF_AL + off);
                }
                uint32_t bh[4][2], bl[4][2];
#pragma unroll
                for (int n16 = 0; n16 < 2; n16++) {
                    const int row = wc * 32 + n16 * 16 + rowSel;
                    const uint32_t off = (uint32_t)(row * 64 + ((chunk ^ rmod) * 16));
                    uint32_t rh[4], rl[4];
                    ldsm4(rh, sb + OFF_BH + off);
                    ldsm4(rl, sb + OFF_BL + off);
                    bh[n16 * 2][0] = rh[0]; bh[n16 * 2 + 1][0] = rh[1];
                    bh[n16 * 2][1] = rh[2]; bh[n16 * 2 + 1][1] = rh[3];
                    bl[n16 * 2][0] = rl[0]; bl[n16 * 2 + 1][0] = rl[1];
                    bl[n16 * 2][1] = rl[2]; bl[n16 * 2 + 1][1] = rl[3];
                }
#pragma unroll
                for (int mt = 0; mt < 4; mt++)
#pragma unroll
                    for (int nt = 0; nt < 4; nt++) {
                        mma16816(acc[mt][nt], ah[mt], bh[nt]);
                        mma16816(acc[mt][nt], ah[mt], bl[nt]);
                        mma16816(acc[mt][nt], al[mt], bh[nt]);
                    }
            }
            __syncthreads();
        }
    }
};

__device__ __forceinline__ void split_store(__nv_bfloat16* oh, __nv_bfloat16* ol,
                                            size_t off, float v0, float v1) {
    __nv_bfloat16 h0 = __float2bfloat16(v0);
    __nv_bfloat16 h1 = __float2bfloat16(v1);
    *(__nv_bfloat162*)(oh + off) = __halves2bfloat162(h0, h1);
    *(__nv_bfloat162*)(ol + off) = __halves2bfloat162(
        __float2bfloat16(v0 - __bfloat162float(h0)),
        __float2bfloat16(v1 - __bfloat162float(h1)));
}

// ---- merged pre/Q/K/V GEMM ------------------------------------------------
__global__ __launch_bounds__(256) void hmma_qkv(
    const __nv_bfloat16* __restrict__ xh, const __nv_bfloat16* __restrict__ xl,
    const __nv_bfloat16* wpreh, const __nv_bfloat16* wprel,
    const __nv_bfloat16* wqh, const __nv_bfloat16* wql,
    const __nv_bfloat16* wkh, const __nv_bfloat16* wkl,
    const __nv_bfloat16* wvh, const __nv_bfloat16* wvl,
    const float* __restrict__ bpre,
    __nv_bfloat16* preh, __nv_bfloat16* prel,
    __nv_bfloat16* qh, __nv_bfloat16* ql,
    __nv_bfloat16* kh, __nv_bfloat16* kl,
    __nv_bfloat16* vh, __nv_bfloat16* vl)
{
    extern __shared__ char smem_raw[];
    GemmCore gc_;
    gc_.init(smem_to_u32(smem_raw), threadIdx.x);

    const int g    = blockIdx.x >> 3;
    const int col0 = (blockIdx.x & 7) * 128;
    const int row0 = blockIdx.y * 128;

    const __nv_bfloat16* Bh[4] = {wpreh, wqh, wkh, wvh};
    const __nv_bfloat16* Bl[4] = {wprel, wql, wkl, wvl};
    __nv_bfloat16* OH[4] = {preh, qh, kh, vh};
    __nv_bfloat16* OL[4] = {prel, ql, kl, vl};

    float acc[4][4][4];
    gc_.run(xh, xl, Bh[g], Bl[g], row0, col0, acc);

    const int r0g = row0 + gc_.wr * 64 + (gc_.lane >> 2);
    const int c0g = col0 + gc_.wc * 32 + (gc_.lane & 3) * 2;
#pragma unroll
    for (int mt = 0; mt < 4; mt++) {
#pragma unroll
        for (int nt = 0; nt < 4; nt++) {
            const int gcc = c0g + nt * 8;
#pragma unroll
            for (int half = 0; half < 2; half++) {
                const int gr = r0g + mt * 16 + half * 8;
                float v0 = acc[mt][nt][half * 2 + 0];
                float v1 = acc[mt][nt][half * 2 + 1];
                if (g == 0) {
                    v0 += bpre[gcc]; v1 += bpre[gcc + 1];
                    v0 = v0 / (1.0f + __expf(-v0));
                    v1 = v1 / (1.0f + __expf(-v1));
                    split_store(OH[0], OL[0], (size_t)gr * CC + gcc, v0, v1);
                } else {
                    const int b = gr >> 10, n = gr & (NN - 1);
                    const int h = gcc >> 6, dh = gcc & 63;
                    const size_t o = ((size_t)(b * HH + h) * NN + n) * DH + dh;
                    split_store(OH[g], OL[g], o, v0, v1);
                }
            }
        }
    }
}

// ---- logits (symmetric, upper-tri tiles) + proj/resid GEMM ----------------
__global__ __launch_bounds__(256) void hmma_gemm(
    const __nv_bfloat16* __restrict__ Ah, const __nv_bfloat16* __restrict__ Al,
    const __nv_bfloat16* __restrict__ Bh, const __nv_bfloat16* __restrict__ Bl,
    const float* __restrict__ bias, const float* __restrict__ resid,
    float* __restrict__ outF, int mode, long long bsA, long long bsB)
{
    extern __shared__ char smem_raw[];
    GemmCore gc_;
    gc_.init(smem_to_u32(smem_raw), threadIdx.x);

    int row0, col0, ti = 0, tj = 0;
    if (mode == EPI_LOGITS) {
        int li = blockIdx.x, rem = 8;
        while (li >= rem) { li -= rem; rem--; ti++; }
        tj = ti + li;
        row0 = ti * 128; col0 = tj * 128;
    } else {
        row0 = blockIdx.y * 128;
        col0 = blockIdx.x * 128;
    }
    const int z = blockIdx.z;
    const __nv_bfloat16* Ahb = Ah + (size_t)z * bsA;
    const __nv_bfloat16* Alb = Al + (size_t)z * bsA;
    const __nv_bfloat16* Bhb = Bh + (size_t)z * bsB;
    const __nv_bfloat16* Blb = Bl + (size_t)z * bsB;

    float acc[4][4][4];
    gc_.run(Ahb, Alb, Bhb, Blb, row0, col0, acc);

    const int r0g = row0 + gc_.wr * 64 + (gc_.lane >> 2);
    const int c0g = col0 + gc_.wc * 32 + (gc_.lane & 3) * 2;
#pragma unroll
    for (int mt = 0; mt < 4; mt++) {
#pragma unroll
        for (int nt = 0; nt < 4; nt++) {
            const int gcc = c0g + nt * 8;
#pragma unroll
            for (int half = 0; half < 2; half++) {
                const int gr = r0g + mt * 16 + half * 8;
                float v0 = acc[mt][nt][half * 2 + 0];
                float v1 = acc[mt][nt][half * 2 + 1];
                if (mode == EPI_LOGITS) {
                    float* base = outF + (size_t)z * NN * NN;
                    v0 *= 0.03125f; v1 *= 0.03125f;
                    base[(size_t)gr * NN + gcc]     = v0;
                    base[(size_t)gr * NN + gcc + 1] = v1;
                    if (ti != tj) {
                        base[(size_t)gcc * NN + gr]       = v0;
                        base[(size_t)(gcc + 1) * NN + gr] = v1;
                    }
                } else { // EPI_RESID
                    const size_t ro = (size_t)gr * CC + gcc;
                    outF[ro]     = v0 + bias[gcc]     + resid[ro];
                    outF[ro + 1] = v1 + bias[gcc + 1] + resid[ro + 1];
                }
            }
        }
    }
}

// ======================= HMMA flash attention (128-q tile) =================
// R6 version (known-good 688us config): single-buffered K/V.
#define SMQ_H 0
#define SMQ_L 16384
#define SMK_H 32768
#define SMK_L 40960
#define SMV_H 49152
#define SMV_L 57344
#define SMEM_FATT 65536

__global__ __launch_bounds__(256, 2) void fattn(
    const __nv_bfloat16* __restrict__ qh, const __nv_bfloat16* __restrict__ ql,
    const __nv_bfloat16* __restrict__ kh, const __nv_bfloat16* __restrict__ kl,
    const __nv_bfloat16* __restrict__ vh, const __nv_bfloat16* __restrict__ vl,
    const float* __restrict__ logits, const float* __restrict__ pi_p,
    __nv_bfloat16* __restrict__ ctxh, __nv_bfloat16* __restrict__ ctxl)
{
    extern __shared__ char sm[];
    const uint32_t sb = smem_to_u32(sm);
    const int t = threadIdx.x, lane = t & 31, w = t >> 5;
    const int bh = blockIdx.y, b = bh >> 4, h = bh & 15;
    const int q0 = blockIdx.x * 128;
    const size_t hoff = (size_t)bh * NN * DH;
    const float pi = pi_p[0];

#pragma unroll
    for (int i = 0; i < 4; i++) {
        const int id = t + i * 256;
        const int r = id >> 3, c = id & 7;
        const uint32_t off = (uint32_t)(r * 128 + ((c ^ (r & 7)) * 16));
        const size_t g = hoff + (size_t)(q0 + r) * DH + c * 8;
        CP_ASYNC16(sb + SMQ_H + off, qh + g);
        CP_ASYNC16(sb + SMQ_L + off, ql + g);
    }
    CP_COMMIT();

    float S[8][4], O[8][4];
#pragma unroll
    for (int j = 0; j < 8; j++)
#pragma unroll
        for (int c = 0; c < 4; c++) O[j][c] = 0.0f;
    float m0 = -1e30f, m1 = -1e30f, l0 = 0.0f, l1 = 0.0f;

    const int qr = w * 16 + (lane >> 2);
    const float* lgr = logits + (size_t)b * NN * NN + (size_t)(q0 + qr) * NN;
    const int rowSel = lane & 15, hiH = lane >> 4;

    for (int kt = 0; kt < 16; kt++) {
        const int mk = kt * 64;
        __syncthreads();
#pragma unroll
        for (int i = 0; i < 2; i++) {
            const int id = t + i * 256;
            const int r = id >> 3, c = id & 7;
            const uint32_t off = (uint32_t)(r * 128 + ((c ^ (r & 7)) * 16));
            const size_t g = hoff + (size_t)(mk + r) * DH + c * 8;
            CP_ASYNC16(sb + SMK_H + off, kh + g);
            CP_ASYNC16(sb + SMK_L + off, kl + g);
            CP_ASYNC16(sb + SMV_H + off, vh + g);
            CP_ASYNC16(sb + SMV_L + off, vl + g);
        }
        CP_COMMIT(); CP_WAIT0();
        __syncthreads();

        // ---- S = Q K^T (3-term) ----
#pragma unroll
        for (int j = 0; j < 8; j++)
#pragma unroll
            for (int c = 0; c < 4; c++) S[j][c] = 0.0f;

#pragma unroll
        for (int kc = 0; kc < 4; kc++) {
            const int chunk = 2 * kc + hiH;
            uint32_t aqh[4], aql[4];
            {
                const int row = w * 16 + rowSel;
                const uint32_t off = (uint32_t)(row * 128 + ((chunk ^ (row & 7)) * 16));
                ldsm4(aqh, sb + SMQ_H + off);
                ldsm4(aql, sb + SMQ_L + off);
            }
#pragma unroll
            for (int j16 = 0; j16 < 4; j16++) {
                const int row = j16 * 16 + rowSel;
                const uint32_t off = (uint32_t)(row * 128 + ((chunk ^ (row & 7)) * 16));
                uint32_t rh[4], rl[4];
                ldsm4(rh, sb + SMK_H + off);
                ldsm4(rl, sb + SMK_L + off);
                uint32_t b0h[2] = {rh[0], rh[2]}, b1h[2] = {rh[1], rh[3]};
                uint32_t b0l[2] = {rl[0], rl[2]}, b1l[2] = {rl[1], rl[3]};
                mma16816(S[2 * j16],     aqh, b0h);
                mma16816(S[2 * j16],     aqh, b0l);
                mma16816(S[2 * j16],     aql, b0h);
                mma16816(S[2 * j16 + 1], aqh, b1h);
                mma16816(S[2 * j16 + 1], aqh, b1l);
                mma16816(S[2 * j16 + 1], aql, b1h);
            }
        }

        // ---- bias + online softmax ----
        float mx0 = -1e30f, mx1 = -1e30f;
#pragma unroll
        for (int j = 0; j < 8; j++) {
            const float2 L0 = *(const float2*)(lgr + mk + j * 8 + (lane & 3) * 2);
            const float2 L1 = *(const float2*)(lgr + 8 * NN + mk + j * 8 + (lane & 3) * 2);
            S[j][0] = S[j][0] * 0.125f + pi * L0.x;
            S[j][1] = S[j][1] * 0.125f + pi * L0.y;
            S[j][2] = S[j][2] * 0.125f + pi * L1.x;
            S[j][3] = S[j][3] * 0.125f + pi * L1.y;
            mx0 = fmaxf(mx0, fmaxf(S[j][0], S[j][1]));
            mx1 = fmaxf(mx1, fmaxf(S[j][2], S[j][3]));
        }
        mx0 = fmaxf(mx0, __shfl_xor_sync(0xffffffffu, mx0, 1));
        mx0 = fmaxf(mx0, __shfl_xor_sync(0xffffffffu, mx0, 2));
        mx1 = fmaxf(mx1, __shfl_xor_sync(0xffffffffu, mx1, 1));
        mx1 = fmaxf(mx1, __shfl_xor_sync(0xffffffffu, mx1, 2));
        const float mn0 = fmaxf(m0, mx0), mn1 = fmaxf(m1, mx1);
        const float a0 = __expf(m0 - mn0), a1 = __expf(m1 - mn1);
        m0 = mn0; m1 = mn1;
        float s0 = 0.0f, s1 = 0.0f;
#pragma unroll
        for (int j = 0; j < 8; j++) {
            S[j][0] = __expf(S[j][0] - mn0); S[j][1] = __expf(S[j][1] - mn0);
            S[j][2] = __expf(S[j][2] - mn1); S[j][3] = __expf(S[j][3] - mn1);
            s0 += S[j][0] + S[j][1];
            s1 += S[j][2] + S[j][3];
        }
        s0 += __shfl_xor_sync(0xffffffffu, s0, 1);
        s0 += __shfl_xor_sync(0xffffffffu, s0, 2);
        s1 += __shfl_xor_sync(0xffffffffu, s1, 1);
        s1 += __shfl_xor_sync(0xffffffffu, s1, 2);
        l0 = l0 * a0 + s0; l1 = l1 * a1 + s1;
#pragma unroll
        for (int j = 0; j < 8; j++) {
            O[j][0] *= a0; O[j][1] *= a0; O[j][2] *= a1; O[j][3] *= a1;
        }

        // ---- O += P V (3-term) ----
#pragma unroll
        for (int kc = 0; kc < 4; kc++) {
            uint32_t ph[4], pl[4];
#pragma unroll
            for (int half = 0; half < 2; half++) {
                const int j = 2 * kc + half;
                float x0 = S[j][0], x1 = S[j][1], x2 = S[j][2], x3 = S[j][3];
                uint32_t hp = pack_bf16(x0, x1);
                uint32_t hq = pack_bf16(x2, x3);
                ph[half * 2 + 0] = hp;
                ph[half * 2 + 1] = hq;
                __nv_bfloat162 hp2 = *(__nv_bfloat162*)&hp;
                __nv_bfloat162 hq2 = *(__nv_bfloat162*)&hq;
                pl[half * 2 + 0] = pack_bf16(x0 - __bfloat162float(__low2bfloat16(hp2)),
                                             x1 - __bfloat162float(__high2bfloat16(hp2)));
                pl[half * 2 + 1] = pack_bf16(x2 - __bfloat162float(__low2bfloat16(hq2)),
                                             x3 - __bfloat162float(__high2bfloat16(hq2)));
            }
#pragma unroll
            for (int jc = 0; jc < 4; jc++) {
                const int row = kc * 16 + rowSel;
                const int chunk = 2 * jc + hiH;
                const uint32_t off = (uint32_t)(row * 128 + ((chunk ^ (row & 7)) * 16));
                uint32_t rvh[4], rvl[4];
                ldsm4t(rvh, sb + SMV_H + off);
                ldsm4t(rvl, sb + SMV_L + off);
                uint32_t v0h[2] = {rvh[0], rvh[1]}, v1h[2] = {rvh[2], rvh[3]};
                uint32_t v0l[2] = {rvl[0], rvl[1]}, v1l[2] = {rvl[2], rvl[3]};
                mma16816(O[2 * jc],     ph, v0h);
                mma16816(O[2 * jc],     ph, v0l);
                mma16816(O[2 * jc],     pl, v0h);
                mma16816(O[2 * jc + 1], ph, v1h);
                mma16816(O[2 * jc + 1], ph, v1l);
                mma16816(O[2 * jc + 1], pl, v1h);
            }
        }
    }

    // ---- epilogue ----
    const float inv0 = 1.0f / l0, inv1 = 1.0f / l1;
    const size_t r0o = (size_t)(b * NN + q0 + qr) * CC;
    const size_t r1o = r0o + (size_t)8 * CC;
    const int cb = h * DH + (lane & 3) * 2;
#pragma unroll
    for (int dj = 0; dj < 8; dj++) {
        const int col = cb + dj * 8;
        split_store(ctxh, ctxl, r0o + col, O[dj][0] * inv0, O[dj][1] * inv0);
        split_store(ctxh, ctxl, r1o + col, O[dj][2] * inv1, O[dj][3] * inv1);
    }
}

// ---------------------------------------------------------------------------
extern "C" void kernel_launch(void* const* d_in, const int* in_sizes, int n_in,
                              void* d_out, int out_size)
{
    (void)in_sizes; (void)n_in; (void)out_size;
    const float* x     = (const float*)d_in[0];
    const float* Wq    = (const float*)d_in[1];
    const float* Wk    = (const float*)d_in[2];
    const float* Wv    = (const float*)d_in[3];
    const float* Wproj = (const float*)d_in[4];
    const float* bproj = (const float*)d_in[5];
    const float* Wpre  = (const float*)d_in[6];
    const float* bpre  = (const float*)d_in[7];
    const float* pi    = (const float*)d_in[8];
    float* out = (float*)d_out;

    float* lgp;
    __nv_bfloat16 *xh, *xl, *preh, *prel, *ctxh, *ctxl;
    __nv_bfloat16 *qhp, *qlp, *khp, *klp, *vhp, *vlp;
    __nv_bfloat16 *wpreh, *wprel, *wqh, *wql, *wkh, *wkl, *wvh, *wvl, *wph, *wpl;
    cudaGetSymbolAddress((void**)&lgp,   g_logits);
    cudaGetSymbolAddress((void**)&xh,    g_xh);
    cudaGetSymbolAddress((void**)&xl,    g_xl);
    cudaGetSymbolAddress((void**)&preh,  g_preh);
    cudaGetSymbolAddress((void**)&prel,  g_prel);
    cudaGetSymbolAddress((void**)&ctxh,  g_ctxh);
    cudaGetSymbolAddress((void**)&ctxl,  g_ctxl);
    cudaGetSymbolAddress((void**)&qhp,   g_qh);
    cudaGetSymbolAddress((void**)&qlp,   g_ql);
    cudaGetSymbolAddress((void**)&khp,   g_kh);
    cudaGetSymbolAddress((void**)&klp,   g_kl);
    cudaGetSymbolAddress((void**)&vhp,   g_vh);
    cudaGetSymbolAddress((void**)&vlp,   g_vl);
    cudaGetSymbolAddress((void**)&wpreh, g_wpreh);
    cudaGetSymbolAddress((void**)&wprel, g_wprel);
    cudaGetSymbolAddress((void**)&wqh,   g_wqh);
    cudaGetSymbolAddress((void**)&wql,   g_wql);
    cudaGetSymbolAddress((void**)&wkh,   g_wkh);
    cudaGetSymbolAddress((void**)&wkl,   g_wkl);
    cudaGetSymbolAddress((void**)&wvh,   g_wvh);
    cudaGetSymbolAddress((void**)&wvl,   g_wvl);
    cudaGetSymbolAddress((void**)&wph,   g_wph);
    cudaGetSymbolAddress((void**)&wpl,   g_wpl);

    cudaFuncSetAttribute(hmma_qkv,  cudaFuncAttributeMaxDynamicSharedMemorySize, SMEM_HMMA);
    cudaFuncSetAttribute(hmma_gemm, cudaFuncAttributeMaxDynamicSharedMemorySize, SMEM_HMMA);
    cudaFuncSetAttribute(fattn,     cudaFuncAttributeMaxDynamicSharedMemorySize, SMEM_FATT);

    // ---- prep ----
    dim3 wst(32, 8), wsg(32, 32, 5);
    wsplit_T5<<<wsg, wst>>>(Wpre, Wq, Wk, Wv, Wproj,
                            wpreh, wprel, wqh, wql, wkh, wkl, wvh, wvl, wph, wpl);
    const int n2 = MROWS * CC / 2;
    split2<<<(n2 + 255) / 256, 256>>>((const float2*)x,
        (__nv_bfloat162*)xh, (__nv_bfloat162*)xl, n2);

    // ---- merged pre/Q/K/V GEMM ----
    dim3 mb(256);
    dim3 gqkv(32, MROWS / 128, 1);
    hmma_qkv<<<gqkv, mb, SMEM_HMMA>>>(xh, xl,
        wpreh, wprel, wqh, wql, wkh, wkl, wvh, wvl, bpre,
        preh, prel, qhp, qlp, khp, klp, vhp, vlp);

    // ---- logits GEMM (symmetric: 36 upper-tri tiles/batch) ----
    dim3 glog(36, 1, BB);
    hmma_gemm<<<glog, mb, SMEM_HMMA>>>(preh, prel, preh, prel, nullptr, nullptr,
                                       lgp, EPI_LOGITS,
                                       (long long)NN * CC, (long long)NN * CC);

    // ---- HMMA flash attention ----
    dim3 ga(NN / 128, BB * HH);
    fattn<<<ga, 256, SMEM_FATT>>>(qhp, qlp, khp, klp, vhp, vlp, lgp, pi,
                                  ctxh, ctxl);

    // ---- projection + residual ----
    dim3 gl(CC / 128, MROWS / 128, 1);
    hmma_gemm<<<gl, mb, SMEM_HMMA>>>(ctxh, ctxl, wph, wpl, bproj, x,
                                     out, EPI_RESID, 0, 0);
}

// round 9
// speedup vs baseline: 1.1802x; 1.0211x over previous
#include <cuda_runtime.h>
#include <cuda_bf16.h>
#include <math.h>
#include <stdint.h>

#define BB 4
#define NN 1024
#define CC 1024
#define HH 16
#define DH 64
#define MROWS (BB*NN)   // 4096

// ---------------- scratch (device globals; no allocation allowed) ----------
__device__ float g_logits[BB*NN*NN];               // 16 MB
__device__ __nv_bfloat16 g_xh[MROWS*CC];
__device__ __nv_bfloat16 g_xl[MROWS*CC];
__device__ __nv_bfloat16 g_preh[MROWS*CC];
__device__ __nv_bfloat16 g_prel[MROWS*CC];
__device__ __nv_bfloat16 g_ctxh[MROWS*CC];
__device__ __nv_bfloat16 g_ctxl[MROWS*CC];
__device__ __nv_bfloat16 g_qh[BB*HH*NN*DH], g_ql[BB*HH*NN*DH];
__device__ __nv_bfloat16 g_kh[BB*HH*NN*DH], g_kl[BB*HH*NN*DH];
__device__ __nv_bfloat16 g_vh[BB*HH*NN*DH], g_vl[BB*HH*NN*DH];
__device__ __nv_bfloat16 g_wpreh[CC*CC], g_wprel[CC*CC];
__device__ __nv_bfloat16 g_wqh[CC*CC],  g_wql[CC*CC];
__device__ __nv_bfloat16 g_wkh[CC*CC],  g_wkl[CC*CC];
__device__ __nv_bfloat16 g_wvh[CC*CC],  g_wvl[CC*CC];
__device__ __nv_bfloat16 g_wph[CC*CC],  g_wpl[CC*CC];

// ======================= portable PTX helpers ==============================
__device__ __forceinline__ uint32_t smem_to_u32(const void* p) {
    uint32_t a;
    asm("{ .reg .u64 t; cvta.to.shared.u64 t, %1; cvt.u32.u64 %0, t; }"
        : "=r"(a) : "l"(p));
    return a;
}
#define CP_ASYNC16(dst, src) \
    asm volatile("cp.async.cg.shared.global [%0], [%1], 16;" \
                 :: "r"(dst), "l"(src) : "memory")
#define CP_COMMIT() asm volatile("cp.async.commit_group;" ::: "memory")
#define CP_WAIT0()  asm volatile("cp.async.wait_group 0;" ::: "memory")

__device__ __forceinline__ void ldsm4(uint32_t* r, uint32_t addr) {
    asm volatile("ldmatrix.sync.aligned.m8n8.x4.shared.b16 {%0,%1,%2,%3}, [%4];"
        : "=r"(r[0]), "=r"(r[1]), "=r"(r[2]), "=r"(r[3]) : "r"(addr));
}
__device__ __forceinline__ void ldsm4t(uint32_t* r, uint32_t addr) {
    asm volatile("ldmatrix.sync.aligned.m8n8.x4.trans.shared.b16 {%0,%1,%2,%3}, [%4];"
        : "=r"(r[0]), "=r"(r[1]), "=r"(r[2]), "=r"(r[3]) : "r"(addr));
}
__device__ __forceinline__ void mma16816(float* c, const uint32_t* a,
                                         const uint32_t* b) {
    asm volatile("mma.sync.aligned.m16n8k16.row.col.f32.bf16.bf16.f32 "
        "{%0,%1,%2,%3}, {%4,%5,%6,%7}, {%8,%9}, {%0,%1,%2,%3};"
        : "+f"(c[0]), "+f"(c[1]), "+f"(c[2]), "+f"(c[3])
        : "r"(a[0]), "r"(a[1]), "r"(a[2]), "r"(a[3]), "r"(b[0]), "r"(b[1]));
}
__device__ __forceinline__ uint32_t pack_bf16(float x, float y) {
    __nv_bfloat162 p = __halves2bfloat162(__float2bfloat16(x), __float2bfloat16(y));
    return *(uint32_t*)&p;
}

// ======================= prep kernels ======================================
__global__ __launch_bounds__(256) void split2(
    const float2* __restrict__ in, __nv_bfloat162* __restrict__ hi,
    __nv_bfloat162* __restrict__ lo, int n2)
{
    int i = blockIdx.x * blockDim.x + threadIdx.x;
    if (i < n2) {
        float2 a = in[i];
        __nv_bfloat16 hx = __float2bfloat16(a.x), hy = __float2bfloat16(a.y);
        float lx = a.x - __bfloat162float(hx), ly = a.y - __bfloat162float(hy);
        hi[i] = __halves2bfloat162(hx, hy);
        lo[i] = __halves2bfloat162(__float2bfloat16(lx), __float2bfloat16(ly));
    }
}

__global__ __launch_bounds__(256) void wsplit_T5(
    const float* __restrict__ W0, const float* __restrict__ W1,
    const float* __restrict__ W2, const float* __restrict__ W3,
    const float* __restrict__ W4,
    __nv_bfloat16* o0h, __nv_bfloat16* o0l, __nv_bfloat16* o1h, __nv_bfloat16* o1l,
    __nv_bfloat16* o2h, __nv_bfloat16* o2l, __nv_bfloat16* o3h, __nv_bfloat16* o3l,
    __nv_bfloat16* o4h, __nv_bfloat16* o4l)
{
    const float* Ws[5] = {W0, W1, W2, W3, W4};
    __nv_bfloat16* Hs[5] = {o0h, o1h, o2h, o3h, o4h};
    __nv_bfloat16* Ls[5] = {o0l, o1l, o2l, o3l, o4l};
    const int z = blockIdx.z;
    const float* W = Ws[z];
    __nv_bfloat16* th = Hs[z];
    __nv_bfloat16* tl = Ls[z];

    __shared__ float s[32][33];
    const int tx = threadIdx.x, ty = threadIdx.y;
    const int n0 = blockIdx.x * 32, k0 = blockIdx.y * 32;
#pragma unroll
    for (int i = ty; i < 32; i += 8)
        s[i][tx] = W[(size_t)(k0 + i) * CC + n0 + tx];
    __syncthreads();
#pragma unroll
    for (int i = ty; i < 32; i += 8) {
        float v = s[tx][i];
        __nv_bfloat16 h = __float2bfloat16(v);
        float l = v - __bfloat162float(h);
        size_t o = (size_t)(n0 + i) * CC + k0 + tx;
        th[o] = h; tl[o] = __float2bfloat16(l);
    }
}

// ======================= HMMA GEMM common machinery ========================
enum { EPI_PRE = 0, EPI_BHND = 1, EPI_LOGITS = 2, EPI_RESID = 3 };

#define OFF_AH 0
#define OFF_AL 8192
#define OFF_BH 16384
#define OFF_BL 24576
#define STAGE_BYTES 32768
#define SMEM_HMMA (2 * STAGE_BYTES)    // 65536

// Conflict-free swizzle key ((r>>1)&3): even/odd rows occupy low/high 64B
// halves of a 128B bank-row; 4 even rows get distinct 16B chunks.
struct GemmCore {
    uint32_t smem_u32;
    int lane, wid, wr, wc, lrow, lc, rowSel, hiH, rmod;
    __device__ __forceinline__ void init(uint32_t smem, int t) {
        smem_u32 = smem;
        lane = t & 31; wid = t >> 5;
        wr = wid & 1; wc = wid >> 1;
        lrow = t >> 2; lc = t & 3;
        rowSel = lane & 15; hiH = lane >> 4; rmod = (rowSel >> 1) & 3;
    }
    __device__ __forceinline__ void load_stage(
        const __nv_bfloat16* Ahb, const __nv_bfloat16* Alb,
        const __nv_bfloat16* Bhb, const __nv_bfloat16* Blb,
        int row0, int col0, int ch, int s) const
    {
        const size_t kb = (size_t)ch * 32 + lc * 8;
        const uint32_t sb = smem_u32 + s * STAGE_BYTES;
#pragma unroll
        for (int i = 0; i < 2; i++) {
            const int r = lrow + i * 64;
            const uint32_t so = (uint32_t)(r * 64 + ((lc ^ ((r >> 1) & 3)) * 16));
            const size_t ga = (size_t)(row0 + r) * CC + kb;
            const size_t gb = (size_t)(col0 + r) * CC + kb;
            CP_ASYNC16(sb + OFF_AH + so, Ahb + ga);
            CP_ASYNC16(sb + OFF_AL + so, Alb + ga);
            CP_ASYNC16(sb + OFF_BH + so, Bhb + gb);
            CP_ASYNC16(sb + OFF_BL + so, Blb + gb);
        }
    }
    // Single-sync mainloop: WAIT0 -> sync -> issue next load -> compute.
    // The top-of-loop sync doubles as the end-of-compute barrier for ch-1,
    // so overwriting buffer (ch+1)&1 (= ch-1's buffer) afterwards is safe.
    __device__ __forceinline__ void run(
        const __nv_bfloat16* Ahb, const __nv_bfloat16* Alb,
        const __nv_bfloat16* Bhb, const __nv_bfloat16* Blb,
        int row0, int col0, float acc[4][4][4]) const
    {
#pragma unroll
        for (int a = 0; a < 4; a++)
#pragma unroll
            for (int b = 0; b < 4; b++)
#pragma unroll
                for (int c = 0; c < 4; c++) acc[a][b][c] = 0.0f;

        load_stage(Ahb, Alb, Bhb, Blb, row0, col0, 0, 0);
        CP_COMMIT();
        for (int ch = 0; ch < 32; ch++) {
            CP_WAIT0();
            __syncthreads();
            if (ch < 31) {
                load_stage(Ahb, Alb, Bhb, Blb, row0, col0, ch + 1, (ch + 1) & 1);
                CP_COMMIT();
            }

            const uint32_t sb = smem_u32 + (ch & 1) * STAGE_BYTES;
#pragma unroll
            for (int k16 = 0; k16 < 2; k16++) {
                const int chunk = k16 * 2 + hiH;
                // B fragments first (shared across all mt)
                uint32_t bh[4][2], bl[4][2];
#pragma unroll
                for (int n16 = 0; n16 < 2; n16++) {
                    const int row = wc * 32 + n16 * 16 + rowSel;
                    const uint32_t off = (uint32_t)(row * 64 + ((chunk ^ rmod) * 16));
                    uint32_t rh[4], rl[4];
                    ldsm4(rh, sb + OFF_BH + off);
                    ldsm4(rl, sb + OFF_BL + off);
                    bh[n16 * 2][0] = rh[0]; bh[n16 * 2 + 1][0] = rh[1];
                    bh[n16 * 2][1] = rh[2]; bh[n16 * 2 + 1][1] = rh[3];
                    bl[n16 * 2][0] = rl[0]; bl[n16 * 2 + 1][0] = rl[1];
                    bl[n16 * 2][1] = rl[2]; bl[n16 * 2 + 1][1] = rl[3];
                }
                // A fragments per mt (fewer live regs -> better scheduling)
#pragma unroll
                for (int mt = 0; mt < 4; mt++) {
                    const int row = wr * 64 + mt * 16 + rowSel;
                    const uint32_t off = (uint32_t)(row * 64 + ((chunk ^ rmod) * 16));
                    uint32_t ah[4], al[4];
                    ldsm4(ah, sb + OFF_AH + off);
                    ldsm4(al, sb + OFF_AL + off);
#pragma unroll
                    for (int nt = 0; nt < 4; nt++) {
                        mma16816(acc[mt][nt], ah, bh[nt]);
                        mma16816(acc[mt][nt], ah, bl[nt]);
                        mma16816(acc[mt][nt], al, bh[nt]);
                    }
                }
            }
        }
    }
};

__device__ __forceinline__ void split_store(__nv_bfloat16* oh, __nv_bfloat16* ol,
                                            size_t off, float v0, float v1) {
    __nv_bfloat16 h0 = __float2bfloat16(v0);
    __nv_bfloat16 h1 = __float2bfloat16(v1);
    *(__nv_bfloat162*)(oh + off) = __halves2bfloat162(h0, h1);
    *(__nv_bfloat162*)(ol + off) = __halves2bfloat162(
        __float2bfloat16(v0 - __bfloat162float(h0)),
        __float2bfloat16(v1 - __bfloat162float(h1)));
}

// ---- merged pre/Q/K/V GEMM ------------------------------------------------
__global__ __launch_bounds__(256) void hmma_qkv(
    const __nv_bfloat16* __restrict__ xh, const __nv_bfloat16* __restrict__ xl,
    const __nv_bfloat16* wpreh, const __nv_bfloat16* wprel,
    const __nv_bfloat16* wqh, const __nv_bfloat16* wql,
    const __nv_bfloat16* wkh, const __nv_bfloat16* wkl,
    const __nv_bfloat16* wvh, const __nv_bfloat16* wvl,
    const float* __restrict__ bpre,
    __nv_bfloat16* preh, __nv_bfloat16* prel,
    __nv_bfloat16* qh, __nv_bfloat16* ql,
    __nv_bfloat16* kh, __nv_bfloat16* kl,
    __nv_bfloat16* vh, __nv_bfloat16* vl)
{
    extern __shared__ char smem_raw[];
    GemmCore gc_;
    gc_.init(smem_to_u32(smem_raw), threadIdx.x);

    const int g    = blockIdx.x >> 3;
    const int col0 = (blockIdx.x & 7) * 128;
    const int row0 = blockIdx.y * 128;

    const __nv_bfloat16* Bh[4] = {wpreh, wqh, wkh, wvh};
    const __nv_bfloat16* Bl[4] = {wprel, wql, wkl, wvl};
    __nv_bfloat16* OH[4] = {preh, qh, kh, vh};
    __nv_bfloat16* OL[4] = {prel, ql, kl, vl};

    float acc[4][4][4];
    gc_.run(xh, xl, Bh[g], Bl[g], row0, col0, acc);

    const int r0g = row0 + gc_.wr * 64 + (gc_.lane >> 2);
    const int c0g = col0 + gc_.wc * 32 + (gc_.lane & 3) * 2;
#pragma unroll
    for (int mt = 0; mt < 4; mt++) {
#pragma unroll
        for (int nt = 0; nt < 4; nt++) {
            const int gcc = c0g + nt * 8;
#pragma unroll
            for (int half = 0; half < 2; half++) {
                const int gr = r0g + mt * 16 + half * 8;
                float v0 = acc[mt][nt][half * 2 + 0];
                float v1 = acc[mt][nt][half * 2 + 1];
                if (g == 0) {
                    v0 += bpre[gcc]; v1 += bpre[gcc + 1];
                    v0 = v0 / (1.0f + __expf(-v0));
                    v1 = v1 / (1.0f + __expf(-v1));
                    split_store(OH[0], OL[0], (size_t)gr * CC + gcc, v0, v1);
                } else {
                    const int b = gr >> 10, n = gr & (NN - 1);
                    const int h = gcc >> 6, dh = gcc & 63;
                    const size_t o = ((size_t)(b * HH + h) * NN + n) * DH + dh;
                    split_store(OH[g], OL[g], o, v0, v1);
                }
            }
        }
    }
}

// ---- logits (symmetric, upper-tri tiles) + proj/resid GEMM ----------------
__global__ __launch_bounds__(256) void hmma_gemm(
    const __nv_bfloat16* __restrict__ Ah, const __nv_bfloat16* __restrict__ Al,
    const __nv_bfloat16* __restrict__ Bh, const __nv_bfloat16* __restrict__ Bl,
    const float* __restrict__ bias, const float* __restrict__ resid,
    float* __restrict__ outF, int mode, long long bsA, long long bsB)
{
    extern __shared__ char smem_raw[];
    GemmCore gc_;
    gc_.init(smem_to_u32(smem_raw), threadIdx.x);

    int row0, col0, ti = 0, tj = 0;
    if (mode == EPI_LOGITS) {
        int li = blockIdx.x, rem = 8;
        while (li >= rem) { li -= rem; rem--; ti++; }
        tj = ti + li;
        row0 = ti * 128; col0 = tj * 128;
    } else {
        row0 = blockIdx.y * 128;
        col0 = blockIdx.x * 128;
    }
    const int z = blockIdx.z;
    const __nv_bfloat16* Ahb = Ah + (size_t)z * bsA;
    const __nv_bfloat16* Alb = Al + (size_t)z * bsA;
    const __nv_bfloat16* Bhb = Bh + (size_t)z * bsB;
    const __nv_bfloat16* Blb = Bl + (size_t)z * bsB;

    float acc[4][4][4];
    gc_.run(Ahb, Alb, Bhb, Blb, row0, col0, acc);

    const int r0g = row0 + gc_.wr * 64 + (gc_.lane >> 2);
    const int c0g = col0 + gc_.wc * 32 + (gc_.lane & 3) * 2;
#pragma unroll
    for (int mt = 0; mt < 4; mt++) {
#pragma unroll
        for (int nt = 0; nt < 4; nt++) {
            const int gcc = c0g + nt * 8;
#pragma unroll
            for (int half = 0; half < 2; half++) {
                const int gr = r0g + mt * 16 + half * 8;
                float v0 = acc[mt][nt][half * 2 + 0];
                float v1 = acc[mt][nt][half * 2 + 1];
                if (mode == EPI_LOGITS) {
                    float* base = outF + (size_t)z * NN * NN;
                    v0 *= 0.03125f; v1 *= 0.03125f;
                    base[(size_t)gr * NN + gcc]     = v0;
                    base[(size_t)gr * NN + gcc + 1] = v1;
                    if (ti != tj) {
                        base[(size_t)gcc * NN + gr]       = v0;
                        base[(size_t)(gcc + 1) * NN + gr] = v1;
                    }
                } else { // EPI_RESID
                    const size_t ro = (size_t)gr * CC + gcc;
                    outF[ro]     = v0 + bias[gcc]     + resid[ro];
                    outF[ro + 1] = v1 + bias[gcc + 1] + resid[ro + 1];
                }
            }
        }
    }
}

// ======================= HMMA flash attention (128-q tile) =================
// Q resident (32KB) + double-buffered K/V (2 x 32KB); single-sync pipeline.
#define SMQ_H 0
#define SMQ_L 16384
#define KVST 32768
#define KV_KH 0
#define KV_KL 8192
#define KV_VH 16384
#define KV_VL 24576
#define SMEM_FATT (32768 + 2 * KVST)    // 98304

__global__ __launch_bounds__(256, 2) void fattn(
    const __nv_bfloat16* __restrict__ qh, const __nv_bfloat16* __restrict__ ql,
    const __nv_bfloat16* __restrict__ kh, const __nv_bfloat16* __restrict__ kl,
    const __nv_bfloat16* __restrict__ vh, const __nv_bfloat16* __restrict__ vl,
    const float* __restrict__ logits, const float* __restrict__ pi_p,
    __nv_bfloat16* __restrict__ ctxh, __nv_bfloat16* __restrict__ ctxl)
{
    extern __shared__ char sm[];
    const uint32_t sb = smem_to_u32(sm);
    const int t = threadIdx.x, lane = t & 31, w = t >> 5;
    const int bh = blockIdx.y, b = bh >> 4, h = bh & 15;
    const int q0 = blockIdx.x * 128;
    const size_t hoff = (size_t)bh * NN * DH;
    const float pi = pi_p[0];

    // Q async load (once)
#pragma unroll
    for (int i = 0; i < 4; i++) {
        const int id = t + i * 256;
        const int r = id >> 3, c = id & 7;
        const uint32_t off = (uint32_t)(r * 128 + ((c ^ (r & 7)) * 16));
        const size_t g = hoff + (size_t)(q0 + r) * DH + c * 8;
        CP_ASYNC16(sb + SMQ_H + off, qh + g);
        CP_ASYNC16(sb + SMQ_L + off, ql + g);
    }
    CP_COMMIT();

    auto load_kv = [&](int kt, int buf) {
        const uint32_t kvb = sb + 32768 + buf * KVST;
#pragma unroll
        for (int i = 0; i < 2; i++) {
            const int id = t + i * 256;
            const int r = id >> 3, c = id & 7;
            const uint32_t off = (uint32_t)(r * 128 + ((c ^ (r & 7)) * 16));
            const size_t g = hoff + (size_t)(kt * 64 + r) * DH + c * 8;
            CP_ASYNC16(kvb + KV_KH + off, kh + g);
            CP_ASYNC16(kvb + KV_KL + off, kl + g);
            CP_ASYNC16(kvb + KV_VH + off, vh + g);
            CP_ASYNC16(kvb + KV_VL + off, vl + g);
        }
    };

    load_kv(0, 0);
    CP_COMMIT();

    float S[8][4], O[8][4];
#pragma unroll
    for (int j = 0; j < 8; j++)
#pragma unroll
        for (int c = 0; c < 4; c++) O[j][c] = 0.0f;
    float m0 = -1e30f, m1 = -1e30f, l0 = 0.0f, l1 = 0.0f;

    const int qr = w * 16 + (lane >> 2);
    const float* lgr = logits + (size_t)b * NN * NN + (size_t)(q0 + qr) * NN;
    const int rowSel = lane & 15, hiH = lane >> 4;

    for (int kt = 0; kt < 16; kt++) {
        const int mk = kt * 64;
        CP_WAIT0();                 // buf kt (and Q on kt=0) ready
        __syncthreads();            // all warps done reading buf kt-1
        if (kt < 15) { load_kv(kt + 1, (kt + 1) & 1); CP_COMMIT(); }

        const uint32_t kvb = sb + 32768 + (kt & 1) * KVST;

        // ---- S = Q K^T (3-term) ----
#pragma unroll
        for (int j = 0; j < 8; j++)
#pragma unroll
            for (int c = 0; c < 4; c++) S[j][c] = 0.0f;

#pragma unroll
        for (int kc = 0; kc < 4; kc++) {
            const int chunk = 2 * kc + hiH;
            uint32_t aqh[4], aql[4];
            {
                const int row = w * 16 + rowSel;
                const uint32_t off = (uint32_t)(row * 128 + ((chunk ^ (row & 7)) * 16));
                ldsm4(aqh, sb + SMQ_H + off);
                ldsm4(aql, sb + SMQ_L + off);
            }
#pragma unroll
            for (int j16 = 0; j16 < 4; j16++) {
                const int row = j16 * 16 + rowSel;
                const uint32_t off = (uint32_t)(row * 128 + ((chunk ^ (row & 7)) * 16));
                uint32_t rh[4], rl[4];
                ldsm4(rh, kvb + KV_KH + off);
                ldsm4(rl, kvb + KV_KL + off);
                uint32_t b0h[2] = {rh[0], rh[2]}, b1h[2] = {rh[1], rh[3]};
                uint32_t b0l[2] = {rl[0], rl[2]}, b1l[2] = {rl[1], rl[3]};
                mma16816(S[2 * j16],     aqh, b0h);
                mma16816(S[2 * j16],     aqh, b0l);
                mma16816(S[2 * j16],     aql, b0h);
                mma16816(S[2 * j16 + 1], aqh, b1h);
                mma16816(S[2 * j16 + 1], aqh, b1l);
                mma16816(S[2 * j16 + 1], aql, b1h);
            }
        }

        // ---- bias + online softmax ----
        float mx0 = -1e30f, mx1 = -1e30f;
#pragma unroll
        for (int j = 0; j < 8; j++) {
            const float2 L0 = *(const float2*)(lgr + mk + j * 8 + (lane & 3) * 2);
            const float2 L1 = *(const float2*)(lgr + 8 * NN + mk + j * 8 + (lane & 3) * 2);
            S[j][0] = S[j][0] * 0.125f + pi * L0.x;
            S[j][1] = S[j][1] * 0.125f + pi * L0.y;
            S[j][2] = S[j][2] * 0.125f + pi * L1.x;
            S[j][3] = S[j][3] * 0.125f + pi * L1.y;
            mx0 = fmaxf(mx0, fmaxf(S[j][0], S[j][1]));
            mx1 = fmaxf(mx1, fmaxf(S[j][2], S[j][3]));
        }
        mx0 = fmaxf(mx0, __shfl_xor_sync(0xffffffffu, mx0, 1));
        mx0 = fmaxf(mx0, __shfl_xor_sync(0xffffffffu, mx0, 2));
        mx1 = fmaxf(mx1, __shfl_xor_sync(0xffffffffu, mx1, 1));
        mx1 = fmaxf(mx1, __shfl_xor_sync(0xffffffffu, mx1, 2));
        const float mn0 = fmaxf(m0, mx0), mn1 = fmaxf(m1, mx1);
        const float a0 = __expf(m0 - mn0), a1 = __expf(m1 - mn1);
        m0 = mn0; m1 = mn1;
        float s0 = 0.0f, s1 = 0.0f;
#pragma unroll
        for (int j = 0; j < 8; j++) {
            S[j][0] = __expf(S[j][0] - mn0); S[j][1] = __expf(S[j][1] - mn0);
            S[j][2] = __expf(S[j][2] - mn1); S[j][3] = __expf(S[j][3] - mn1);
            s0 += S[j][0] + S[j][1];
            s1 += S[j][2] + S[j][3];
        }
        s0 += __shfl_xor_sync(0xffffffffu, s0, 1);
        s0 += __shfl_xor_sync(0xffffffffu, s0, 2);
        s1 += __shfl_xor_sync(0xffffffffu, s1, 1);
        s1 += __shfl_xor_sync(0xffffffffu, s1, 2);
        l0 = l0 * a0 + s0; l1 = l1 * a1 + s1;
#pragma unroll
        for (int j = 0; j < 8; j++) {
            O[j][0] *= a0; O[j][1] *= a0; O[j][2] *= a1; O[j][3] *= a1;
        }

        // ---- O += P V (3-term) ----
#pragma unroll
        for (int kc = 0; kc < 4; kc++) {
            uint32_t ph[4], pl[4];
#pragma unroll
            for (int half = 0; half < 2; half++) {
                const int j = 2 * kc + half;
                float x0 = S[j][0], x1 = S[j][1], x2 = S[j][2], x3 = S[j][3];
                uint32_t hp = pack_bf16(x0, x1);
                uint32_t hq = pack_bf16(x2, x3);
                ph[half * 2 + 0] = hp;
                ph[half * 2 + 1] = hq;
                __nv_bfloat162 hp2 = *(__nv_bfloat162*)&hp;
                __nv_bfloat162 hq2 = *(__nv_bfloat162*)&hq;
                pl[half * 2 + 0] = pack_bf16(x0 - __bfloat162float(__low2bfloat16(hp2)),
                                             x1 - __bfloat162float(__high2bfloat16(hp2)));
                pl[half * 2 + 1] = pack_bf16(x2 - __bfloat162float(__low2bfloat16(hq2)),
                                             x3 - __bfloat162float(__high2bfloat16(hq2)));
            }
#pragma unroll
            for (int jc = 0; jc < 4; jc++) {
                const int row = kc * 16 + rowSel;
                const int chunk = 2 * jc + hiH;
                const uint32_t off = (uint32_t)(row * 128 + ((chunk ^ (row & 7)) * 16));
                uint32_t rvh[4], rvl[4];
                ldsm4t(rvh, kvb + KV_VH + off);
                ldsm4t(rvl, kvb + KV_VL + off);
                uint32_t v0h[2] = {rvh[0], rvh[1]}, v1h[2] = {rvh[2], rvh[3]};
                uint32_t v0l[2] = {rvl[0], rvl[1]}, v1l[2] = {rvl[2], rvl[3]};
                mma16816(O[2 * jc],     ph, v0h);
                mma16816(O[2 * jc],     ph, v0l);
                mma16816(O[2 * jc],     pl, v0h);
                mma16816(O[2 * jc + 1], ph, v1h);
                mma16816(O[2 * jc + 1], ph, v1l);
                mma16816(O[2 * jc + 1], pl, v1h);
            }
        }
    }

    // ---- epilogue ----
    const float inv0 = 1.0f / l0, inv1 = 1.0f / l1;
    const size_t r0o = (size_t)(b * NN + q0 + qr) * CC;
    const size_t r1o = r0o + (size_t)8 * CC;
    const int cb = h * DH + (lane & 3) * 2;
#pragma unroll
    for (int dj = 0; dj < 8; dj++) {
        const int col = cb + dj * 8;
        split_store(ctxh, ctxl, r0o + col, O[dj][0] * inv0, O[dj][1] * inv0);
        split_store(ctxh, ctxl, r1o + col, O[dj][2] * inv1, O[dj][3] * inv1);
    }
}

// ---------------------------------------------------------------------------
extern "C" void kernel_launch(void* const* d_in, const int* in_sizes, int n_in,
                              void* d_out, int out_size)
{
    (void)in_sizes; (void)n_in; (void)out_size;
    const float* x     = (const float*)d_in[0];
    const float* Wq    = (const float*)d_in[1];
    const float* Wk    = (const float*)d_in[2];
    const float* Wv    = (const float*)d_in[3];
    const float* Wproj = (const float*)d_in[4];
    const float* bproj = (const float*)d_in[5];
    const float* Wpre  = (const float*)d_in[6];
    const float* bpre  = (const float*)d_in[7];
    const float* pi    = (const float*)d_in[8];
    float* out = (float*)d_out;

    float* lgp;
    __nv_bfloat16 *xh, *xl, *preh, *prel, *ctxh, *ctxl;
    __nv_bfloat16 *qhp, *qlp, *khp, *klp, *vhp, *vlp;
    __nv_bfloat16 *wpreh, *wprel, *wqh, *wql, *wkh, *wkl, *wvh, *wvl, *wph, *wpl;
    cudaGetSymbolAddress((void**)&lgp,   g_logits);
    cudaGetSymbolAddress((void**)&xh,    g_xh);
    cudaGetSymbolAddress((void**)&xl,    g_xl);
    cudaGetSymbolAddress((void**)&preh,  g_preh);
    cudaGetSymbolAddress((void**)&prel,  g_prel);
    cudaGetSymbolAddress((void**)&ctxh,  g_ctxh);
    cudaGetSymbolAddress((void**)&ctxl,  g_ctxl);
    cudaGetSymbolAddress((void**)&qhp,   g_qh);
    cudaGetSymbolAddress((void**)&qlp,   g_ql);
    cudaGetSymbolAddress((void**)&khp,   g_kh);
    cudaGetSymbolAddress((void**)&klp,   g_kl);
    cudaGetSymbolAddress((void**)&vhp,   g_vh);
    cudaGetSymbolAddress((void**)&vlp,   g_vl);
    cudaGetSymbolAddress((void**)&wpreh, g_wpreh);
    cudaGetSymbolAddress((void**)&wprel, g_wprel);
    cudaGetSymbolAddress((void**)&wqh,   g_wqh);
    cudaGetSymbolAddress((void**)&wql,   g_wql);
    cudaGetSymbolAddress((void**)&wkh,   g_wkh);
    cudaGetSymbolAddress((void**)&wkl,   g_wkl);
    cudaGetSymbolAddress((void**)&wvh,   g_wvh);
    cudaGetSymbolAddress((void**)&wvl,   g_wvl);
    cudaGetSymbolAddress((void**)&wph,   g_wph);
    cudaGetSymbolAddress((void**)&wpl,   g_wpl);

    cudaFuncSetAttribute(hmma_qkv,  cudaFuncAttributeMaxDynamicSharedMemorySize, SMEM_HMMA);
    cudaFuncSetAttribute(hmma_gemm, cudaFuncAttributeMaxDynamicSharedMemorySize, SMEM_HMMA);
    cudaFuncSetAttribute(fattn,     cudaFuncAttributeMaxDynamicSharedMemorySize, SMEM_FATT);

    // ---- prep ----
    dim3 wst(32, 8), wsg(32, 32, 5);
    wsplit_T5<<<wsg, wst>>>(Wpre, Wq, Wk, Wv, Wproj,
                            wpreh, wprel, wqh, wql, wkh, wkl, wvh, wvl, wph, wpl);
    const int n2 = MROWS * CC / 2;
    split2<<<(n2 + 255) / 256, 256>>>((const float2*)x,
        (__nv_bfloat162*)xh, (__nv_bfloat162*)xl, n2);

    // ---- merged pre/Q/K/V GEMM ----
    dim3 mb(256);
    dim3 gqkv(32, MROWS / 128, 1);
    hmma_qkv<<<gqkv, mb, SMEM_HMMA>>>(xh, xl,
        wpreh, wprel, wqh, wql, wkh, wkl, wvh, wvl, bpre,
        preh, prel, qhp, qlp, khp, klp, vhp, vlp);

    // ---- logits GEMM (symmetric: 36 upper-tri tiles/batch) ----
    dim3 glog(36, 1, BB);
    hmma_gemm<<<glog, mb, SMEM_HMMA>>>(preh, prel, preh, prel, nullptr, nullptr,
                                       lgp, EPI_LOGITS,
                                       (long long)NN * CC, (long long)NN * CC);

    // ---- HMMA flash attention ----
    dim3 ga(NN / 128, BB * HH);
    fattn<<<ga, 256, SMEM_FATT>>>(qhp, qlp, khp, klp, vhp, vlp, lgp, pi,
                                  ctxh, ctxl);

    // ---- projection + residual ----
    dim3 gl(CC / 128, MROWS / 128, 1);
    hmma_gemm<<<gl, mb, SMEM_HMMA>>>(ctxh, ctxl, wph, wpl, bproj, x,
                                     out, EPI_RESID, 0, 0);
}

// round 10
// speedup vs baseline: 1.1936x; 1.0113x over previous
#include <cuda_runtime.h>
#include <cuda_bf16.h>
#include <math.h>
#include <stdint.h>

#define BB 4
#define NN 1024
#define CC 1024
#define HH 16
#define DH 64
#define MROWS (BB*NN)   // 4096

// ---------------- scratch (device globals; no allocation allowed) ----------
__device__ float g_logits[BB*NN*NN];               // 16 MB
__device__ __nv_bfloat16 g_xh[MROWS*CC];
__device__ __nv_bfloat16 g_xl[MROWS*CC];
__device__ __nv_bfloat16 g_preh[MROWS*CC];
__device__ __nv_bfloat16 g_prel[MROWS*CC];
__device__ __nv_bfloat16 g_ctxh[MROWS*CC];
__device__ __nv_bfloat16 g_ctxl[MROWS*CC];
__device__ __nv_bfloat16 g_qh[BB*HH*NN*DH], g_ql[BB*HH*NN*DH];
__device__ __nv_bfloat16 g_kh[BB*HH*NN*DH], g_kl[BB*HH*NN*DH];
__device__ __nv_bfloat16 g_vh[BB*HH*NN*DH], g_vl[BB*HH*NN*DH];
__device__ __nv_bfloat16 g_wpreh[CC*CC], g_wprel[CC*CC];
__device__ __nv_bfloat16 g_wqh[CC*CC],  g_wql[CC*CC];
__device__ __nv_bfloat16 g_wkh[CC*CC],  g_wkl[CC*CC];
__device__ __nv_bfloat16 g_wvh[CC*CC],  g_wvl[CC*CC];
__device__ __nv_bfloat16 g_wph[CC*CC],  g_wpl[CC*CC];

// ======================= portable PTX helpers ==============================
__device__ __forceinline__ uint32_t smem_to_u32(const void* p) {
    uint32_t a;
    asm("{ .reg .u64 t; cvta.to.shared.u64 t, %1; cvt.u32.u64 %0, t; }"
        : "=r"(a) : "l"(p));
    return a;
}
#define CP_ASYNC16(dst, src) \
    asm volatile("cp.async.cg.shared.global [%0], [%1], 16;" \
                 :: "r"(dst), "l"(src) : "memory")
#define CP_COMMIT() asm volatile("cp.async.commit_group;" ::: "memory")
#define CP_WAIT0()  asm volatile("cp.async.wait_group 0;" ::: "memory")

__device__ __forceinline__ void ldsm4(uint32_t* r, uint32_t addr) {
    asm volatile("ldmatrix.sync.aligned.m8n8.x4.shared.b16 {%0,%1,%2,%3}, [%4];"
        : "=r"(r[0]), "=r"(r[1]), "=r"(r[2]), "=r"(r[3]) : "r"(addr));
}
__device__ __forceinline__ void ldsm4t(uint32_t* r, uint32_t addr) {
    asm volatile("ldmatrix.sync.aligned.m8n8.x4.trans.shared.b16 {%0,%1,%2,%3}, [%4];"
        : "=r"(r[0]), "=r"(r[1]), "=r"(r[2]), "=r"(r[3]) : "r"(addr));
}
__device__ __forceinline__ void mma16816(float* c, const uint32_t* a,
                                         const uint32_t* b) {
    asm volatile("mma.sync.aligned.m16n8k16.row.col.f32.bf16.bf16.f32 "
        "{%0,%1,%2,%3}, {%4,%5,%6,%7}, {%8,%9}, {%0,%1,%2,%3};"
        : "+f"(c[0]), "+f"(c[1]), "+f"(c[2]), "+f"(c[3])
        : "r"(a[0]), "r"(a[1]), "r"(a[2]), "r"(a[3]), "r"(b[0]), "r"(b[1]));
}
__device__ __forceinline__ uint32_t pack_bf16(float x, float y) {
    __nv_bfloat162 p = __halves2bfloat162(__float2bfloat16(x), __float2bfloat16(y));
    return *(uint32_t*)&p;
}

// ======================= prep kernels ======================================
__global__ __launch_bounds__(256) void split2(
    const float2* __restrict__ in, __nv_bfloat162* __restrict__ hi,
    __nv_bfloat162* __restrict__ lo, int n2)
{
    int i = blockIdx.x * blockDim.x + threadIdx.x;
    if (i < n2) {
        float2 a = in[i];
        __nv_bfloat16 hx = __float2bfloat16(a.x), hy = __float2bfloat16(a.y);
        float lx = a.x - __bfloat162float(hx), ly = a.y - __bfloat162float(hy);
        hi[i] = __halves2bfloat162(hx, hy);
        lo[i] = __halves2bfloat162(__float2bfloat16(lx), __float2bfloat16(ly));
    }
}

__global__ __launch_bounds__(256) void wsplit_T5(
    const float* __restrict__ W0, const float* __restrict__ W1,
    const float* __restrict__ W2, const float* __restrict__ W3,
    const float* __restrict__ W4,
    __nv_bfloat16* o0h, __nv_bfloat16* o0l, __nv_bfloat16* o1h, __nv_bfloat16* o1l,
    __nv_bfloat16* o2h, __nv_bfloat16* o2l, __nv_bfloat16* o3h, __nv_bfloat16* o3l,
    __nv_bfloat16* o4h, __nv_bfloat16* o4l)
{
    const float* Ws[5] = {W0, W1, W2, W3, W4};
    __nv_bfloat16* Hs[5] = {o0h, o1h, o2h, o3h, o4h};
    __nv_bfloat16* Ls[5] = {o0l, o1l, o2l, o3l, o4l};
    const int z = blockIdx.z;
    const float* W = Ws[z];
    __nv_bfloat16* th = Hs[z];
    __nv_bfloat16* tl = Ls[z];

    __shared__ float s[32][33];
    const int tx = threadIdx.x, ty = threadIdx.y;
    const int n0 = blockIdx.x * 32, k0 = blockIdx.y * 32;
#pragma unroll
    for (int i = ty; i < 32; i += 8)
        s[i][tx] = W[(size_t)(k0 + i) * CC + n0 + tx];
    __syncthreads();
#pragma unroll
    for (int i = ty; i < 32; i += 8) {
        float v = s[tx][i];
        __nv_bfloat16 h = __float2bfloat16(v);
        float l = v - __bfloat162float(h);
        size_t o = (size_t)(n0 + i) * CC + k0 + tx;
        th[o] = h; tl[o] = __float2bfloat16(l);
    }
}

// ======================= HMMA GEMM common machinery ========================
enum { EPI_PRE = 0, EPI_BHND = 1, EPI_LOGITS = 2, EPI_RESID = 3 };

#define OFF_AH 0
#define OFF_AL 8192
#define OFF_BH 16384
#define OFF_BL 24576
#define STAGE_BYTES 32768
#define SMEM_HMMA (2 * STAGE_BYTES)    // 65536

// Conflict-free swizzle key ((r>>1)&3). Term-major MMA ordering: consecutive
// MMAs target different accumulators (RAW distance 4, was 1).
struct GemmCore {
    uint32_t smem_u32;
    int lane, wid, wr, wc, lrow, lc, rowSel, hiH, rmod;
    __device__ __forceinline__ void init(uint32_t smem, int t) {
        smem_u32 = smem;
        lane = t & 31; wid = t >> 5;
        wr = wid & 1; wc = wid >> 1;
        lrow = t >> 2; lc = t & 3;
        rowSel = lane & 15; hiH = lane >> 4; rmod = (rowSel >> 1) & 3;
    }
    __device__ __forceinline__ void load_stage(
        const __nv_bfloat16* Ahb, const __nv_bfloat16* Alb,
        const __nv_bfloat16* Bhb, const __nv_bfloat16* Blb,
        int row0, int col0, int ch, int s) const
    {
        const size_t kb = (size_t)ch * 32 + lc * 8;
        const uint32_t sb = smem_u32 + s * STAGE_BYTES;
#pragma unroll
        for (int i = 0; i < 2; i++) {
            const int r = lrow + i * 64;
            const uint32_t so = (uint32_t)(r * 64 + ((lc ^ ((r >> 1) & 3)) * 16));
            const size_t ga = (size_t)(row0 + r) * CC + kb;
            const size_t gb = (size_t)(col0 + r) * CC + kb;
            CP_ASYNC16(sb + OFF_AH + so, Ahb + ga);
            CP_ASYNC16(sb + OFF_AL + so, Alb + ga);
            CP_ASYNC16(sb + OFF_BH + so, Bhb + gb);
            CP_ASYNC16(sb + OFF_BL + so, Blb + gb);
        }
    }
    __device__ __forceinline__ void run(
        const __nv_bfloat16* Ahb, const __nv_bfloat16* Alb,
        const __nv_bfloat16* Bhb, const __nv_bfloat16* Blb,
        int row0, int col0, float acc[4][4][4]) const
    {
#pragma unroll
        for (int a = 0; a < 4; a++)
#pragma unroll
            for (int b = 0; b < 4; b++)
#pragma unroll
                for (int c = 0; c < 4; c++) acc[a][b][c] = 0.0f;

        load_stage(Ahb, Alb, Bhb, Blb, row0, col0, 0, 0);
        CP_COMMIT();
        for (int ch = 0; ch < 32; ch++) {
            CP_WAIT0();
            __syncthreads();
            if (ch < 31) {
                load_stage(Ahb, Alb, Bhb, Blb, row0, col0, ch + 1, (ch + 1) & 1);
                CP_COMMIT();
            }

            const uint32_t sb = smem_u32 + (ch & 1) * STAGE_BYTES;
#pragma unroll
            for (int k16 = 0; k16 < 2; k16++) {
                const int chunk = k16 * 2 + hiH;
                uint32_t bh[4][2], bl[4][2];
#pragma unroll
                for (int n16 = 0; n16 < 2; n16++) {
                    const int row = wc * 32 + n16 * 16 + rowSel;
                    const uint32_t off = (uint32_t)(row * 64 + ((chunk ^ rmod) * 16));
                    uint32_t rh[4], rl[4];
                    ldsm4(rh, sb + OFF_BH + off);
                    ldsm4(rl, sb + OFF_BL + off);
                    bh[n16 * 2][0] = rh[0]; bh[n16 * 2 + 1][0] = rh[1];
                    bh[n16 * 2][1] = rh[2]; bh[n16 * 2 + 1][1] = rh[3];
                    bl[n16 * 2][0] = rl[0]; bl[n16 * 2 + 1][0] = rl[1];
                    bl[n16 * 2][1] = rl[2]; bl[n16 * 2 + 1][1] = rl[3];
                }
#pragma unroll
                for (int mt = 0; mt < 4; mt++) {
                    const int row = wr * 64 + mt * 16 + rowSel;
                    const uint32_t off = (uint32_t)(row * 64 + ((chunk ^ rmod) * 16));
                    uint32_t ah[4], al[4];
                    ldsm4(ah, sb + OFF_AH + off);
                    ldsm4(al, sb + OFF_AL + off);
                    // term-major: per-acc order stays hh -> hl -> lh, but
                    // consecutive instructions hit different accumulators.
#pragma unroll
                    for (int nt = 0; nt < 4; nt++) mma16816(acc[mt][nt], ah, bh[nt]);
#pragma unroll
                    for (int nt = 0; nt < 4; nt++) mma16816(acc[mt][nt], ah, bl[nt]);
#pragma unroll
                    for (int nt = 0; nt < 4; nt++) mma16816(acc[mt][nt], al, bh[nt]);
                }
            }
        }
    }
};

__device__ __forceinline__ void split_store(__nv_bfloat16* oh, __nv_bfloat16* ol,
                                            size_t off, float v0, float v1) {
    __nv_bfloat16 h0 = __float2bfloat16(v0);
    __nv_bfloat16 h1 = __float2bfloat16(v1);
    *(__nv_bfloat162*)(oh + off) = __halves2bfloat162(h0, h1);
    *(__nv_bfloat162*)(ol + off) = __halves2bfloat162(
        __float2bfloat16(v0 - __bfloat162float(h0)),
        __float2bfloat16(v1 - __bfloat162float(h1)));
}

// ---- merged pre/Q/K/V GEMM ------------------------------------------------
__global__ __launch_bounds__(256) void hmma_qkv(
    const __nv_bfloat16* __restrict__ xh, const __nv_bfloat16* __restrict__ xl,
    const __nv_bfloat16* wpreh, const __nv_bfloat16* wprel,
    const __nv_bfloat16* wqh, const __nv_bfloat16* wql,
    const __nv_bfloat16* wkh, const __nv_bfloat16* wkl,
    const __nv_bfloat16* wvh, const __nv_bfloat16* wvl,
    const float* __restrict__ bpre,
    __nv_bfloat16* preh, __nv_bfloat16* prel,
    __nv_bfloat16* qh, __nv_bfloat16* ql,
    __nv_bfloat16* kh, __nv_bfloat16* kl,
    __nv_bfloat16* vh, __nv_bfloat16* vl)
{
    extern __shared__ char smem_raw[];
    GemmCore gc_;
    gc_.init(smem_to_u32(smem_raw), threadIdx.x);

    const int g    = blockIdx.x >> 3;
    const int col0 = (blockIdx.x & 7) * 128;
    const int row0 = blockIdx.y * 128;

    const __nv_bfloat16* Bh[4] = {wpreh, wqh, wkh, wvh};
    const __nv_bfloat16* Bl[4] = {wprel, wql, wkl, wvl};
    __nv_bfloat16* OH[4] = {preh, qh, kh, vh};
    __nv_bfloat16* OL[4] = {prel, ql, kl, vl};

    float acc[4][4][4];
    gc_.run(xh, xl, Bh[g], Bl[g], row0, col0, acc);

    const int r0g = row0 + gc_.wr * 64 + (gc_.lane >> 2);
    const int c0g = col0 + gc_.wc * 32 + (gc_.lane & 3) * 2;
#pragma unroll
    for (int mt = 0; mt < 4; mt++) {
#pragma unroll
        for (int nt = 0; nt < 4; nt++) {
            const int gcc = c0g + nt * 8;
#pragma unroll
            for (int half = 0; half < 2; half++) {
                const int gr = r0g + mt * 16 + half * 8;
                float v0 = acc[mt][nt][half * 2 + 0];
                float v1 = acc[mt][nt][half * 2 + 1];
                if (g == 0) {
                    v0 += bpre[gcc]; v1 += bpre[gcc + 1];
                    v0 = v0 / (1.0f + __expf(-v0));
                    v1 = v1 / (1.0f + __expf(-v1));
                    split_store(OH[0], OL[0], (size_t)gr * CC + gcc, v0, v1);
                } else {
                    const int b = gr >> 10, n = gr & (NN - 1);
                    const int h = gcc >> 6, dh = gcc & 63;
                    const size_t o = ((size_t)(b * HH + h) * NN + n) * DH + dh;
                    split_store(OH[g], OL[g], o, v0, v1);
                }
            }
        }
    }
}

// ---- logits (symmetric, upper-tri tiles) + proj/resid GEMM ----------------
__global__ __launch_bounds__(256) void hmma_gemm(
    const __nv_bfloat16* __restrict__ Ah, const __nv_bfloat16* __restrict__ Al,
    const __nv_bfloat16* __restrict__ Bh, const __nv_bfloat16* __restrict__ Bl,
    const float* __restrict__ bias, const float* __restrict__ resid,
    float* __restrict__ outF, int mode, long long bsA, long long bsB)
{
    extern __shared__ char smem_raw[];
    GemmCore gc_;
    gc_.init(smem_to_u32(smem_raw), threadIdx.x);

    int row0, col0, ti = 0, tj = 0;
    if (mode == EPI_LOGITS) {
        int li = blockIdx.x, rem = 8;
        while (li >= rem) { li -= rem; rem--; ti++; }
        tj = ti + li;
        row0 = ti * 128; col0 = tj * 128;
    } else {
        row0 = blockIdx.y * 128;
        col0 = blockIdx.x * 128;
    }
    const int z = blockIdx.z;
    const __nv_bfloat16* Ahb = Ah + (size_t)z * bsA;
    const __nv_bfloat16* Alb = Al + (size_t)z * bsA;
    const __nv_bfloat16* Bhb = Bh + (size_t)z * bsB;
    const __nv_bfloat16* Blb = Bl + (size_t)z * bsB;

    float acc[4][4][4];
    gc_.run(Ahb, Alb, Bhb, Blb, row0, col0, acc);

    const int r0g = row0 + gc_.wr * 64 + (gc_.lane >> 2);
    const int c0g = col0 + gc_.wc * 32 + (gc_.lane & 3) * 2;
#pragma unroll
    for (int mt = 0; mt < 4; mt++) {
#pragma unroll
        for (int nt = 0; nt < 4; nt++) {
            const int gcc = c0g + nt * 8;
#pragma unroll
            for (int half = 0; half < 2; half++) {
                const int gr = r0g + mt * 16 + half * 8;
                float v0 = acc[mt][nt][half * 2 + 0];
                float v1 = acc[mt][nt][half * 2 + 1];
                if (mode == EPI_LOGITS) {
                    float* base = outF + (size_t)z * NN * NN;
                    v0 *= 0.03125f; v1 *= 0.03125f;
                    base[(size_t)gr * NN + gcc]     = v0;
                    base[(size_t)gr * NN + gcc + 1] = v1;
                    if (ti != tj) {
                        base[(size_t)gcc * NN + gr]       = v0;
                        base[(size_t)(gcc + 1) * NN + gr] = v1;
                    }
                } else { // EPI_RESID
                    const size_t ro = (size_t)gr * CC + gcc;
                    outF[ro]     = v0 + bias[gcc]     + resid[ro];
                    outF[ro + 1] = v1 + bias[gcc + 1] + resid[ro + 1];
                }
            }
        }
    }
}

// ======================= HMMA flash attention (128-q tile) =================
// Q resident (32KB) + double-buffered K/V (2 x 32KB); single-sync pipeline.
#define SMQ_H 0
#define SMQ_L 16384
#define KVST 32768
#define KV_KH 0
#define KV_KL 8192
#define KV_VH 16384
#define KV_VL 24576
#define SMEM_FATT (32768 + 2 * KVST)    // 98304

__global__ __launch_bounds__(256, 2) void fattn(
    const __nv_bfloat16* __restrict__ qh, const __nv_bfloat16* __restrict__ ql,
    const __nv_bfloat16* __restrict__ kh, const __nv_bfloat16* __restrict__ kl,
    const __nv_bfloat16* __restrict__ vh, const __nv_bfloat16* __restrict__ vl,
    const float* __restrict__ logits, const float* __restrict__ pi_p,
    __nv_bfloat16* __restrict__ ctxh, __nv_bfloat16* __restrict__ ctxl)
{
    extern __shared__ char sm[];
    const uint32_t sb = smem_to_u32(sm);
    const int t = threadIdx.x, lane = t & 31, w = t >> 5;
    const int bh = blockIdx.y, b = bh >> 4, h = bh & 15;
    const int q0 = blockIdx.x * 128;
    const size_t hoff = (size_t)bh * NN * DH;
    const float pi = pi_p[0];

    // Q async load (once)
#pragma unroll
    for (int i = 0; i < 4; i++) {
        const int id = t + i * 256;
        const int r = id >> 3, c = id & 7;
        const uint32_t off = (uint32_t)(r * 128 + ((c ^ (r & 7)) * 16));
        const size_t g = hoff + (size_t)(q0 + r) * DH + c * 8;
        CP_ASYNC16(sb + SMQ_H + off, qh + g);
        CP_ASYNC16(sb + SMQ_L + off, ql + g);
    }
    CP_COMMIT();

    auto load_kv = [&](int kt, int buf) {
        const uint32_t kvb = sb + 32768 + buf * KVST;
#pragma unroll
        for (int i = 0; i < 2; i++) {
            const int id = t + i * 256;
            const int r = id >> 3, c = id & 7;
            const uint32_t off = (uint32_t)(r * 128 + ((c ^ (r & 7)) * 16));
            const size_t g = hoff + (size_t)(kt * 64 + r) * DH + c * 8;
            CP_ASYNC16(kvb + KV_KH + off, kh + g);
            CP_ASYNC16(kvb + KV_KL + off, kl + g);
            CP_ASYNC16(kvb + KV_VH + off, vh + g);
            CP_ASYNC16(kvb + KV_VL + off, vl + g);
        }
    };

    load_kv(0, 0);
    CP_COMMIT();

    float S[8][4], O[8][4];
#pragma unroll
    for (int j = 0; j < 8; j++)
#pragma unroll
        for (int c = 0; c < 4; c++) O[j][c] = 0.0f;
    float m0 = -1e30f, m1 = -1e30f, l0 = 0.0f, l1 = 0.0f;

    const int qr = w * 16 + (lane >> 2);
    const float* lgr = logits + (size_t)b * NN * NN + (size_t)(q0 + qr) * NN;
    const int rowSel = lane & 15, hiH = lane >> 4;

    for (int kt = 0; kt < 16; kt++) {
        const int mk = kt * 64;
        CP_WAIT0();
        __syncthreads();
        if (kt < 15) { load_kv(kt + 1, (kt + 1) & 1); CP_COMMIT(); }

        const uint32_t kvb = sb + 32768 + (kt & 1) * KVST;

        // ---- S = Q K^T (3-term, term-major within j16: distance-2 chains) ----
#pragma unroll
        for (int j = 0; j < 8; j++)
#pragma unroll
            for (int c = 0; c < 4; c++) S[j][c] = 0.0f;

#pragma unroll
        for (int kc = 0; kc < 4; kc++) {
            const int chunk = 2 * kc + hiH;
            uint32_t aqh[4], aql[4];
            {
                const int row = w * 16 + rowSel;
                const uint32_t off = (uint32_t)(row * 128 + ((chunk ^ (row & 7)) * 16));
                ldsm4(aqh, sb + SMQ_H + off);
                ldsm4(aql, sb + SMQ_L + off);
            }
#pragma unroll
            for (int j16 = 0; j16 < 4; j16++) {
                const int row = j16 * 16 + rowSel;
                const uint32_t off = (uint32_t)(row * 128 + ((chunk ^ (row & 7)) * 16));
                uint32_t rh[4], rl[4];
                ldsm4(rh, kvb + KV_KH + off);
                ldsm4(rl, kvb + KV_KL + off);
                uint32_t b0h[2] = {rh[0], rh[2]}, b1h[2] = {rh[1], rh[3]};
                uint32_t b0l[2] = {rl[0], rl[2]}, b1l[2] = {rl[1], rl[3]};
                mma16816(S[2 * j16],     aqh, b0h);
                mma16816(S[2 * j16 + 1], aqh, b1h);
                mma16816(S[2 * j16],     aqh, b0l);
                mma16816(S[2 * j16 + 1], aqh, b1l);
                mma16816(S[2 * j16],     aql, b0h);
                mma16816(S[2 * j16 + 1], aql, b1h);
            }
        }

        // ---- bias + online softmax ----
        float mx0 = -1e30f, mx1 = -1e30f;
#pragma unroll
        for (int j = 0; j < 8; j++) {
            const float2 L0 = *(const float2*)(lgr + mk + j * 8 + (lane & 3) * 2);
            const float2 L1 = *(const float2*)(lgr + 8 * NN + mk + j * 8 + (lane & 3) * 2);
            S[j][0] = S[j][0] * 0.125f + pi * L0.x;
            S[j][1] = S[j][1] * 0.125f + pi * L0.y;
            S[j][2] = S[j][2] * 0.125f + pi * L1.x;
            S[j][3] = S[j][3] * 0.125f + pi * L1.y;
            mx0 = fmaxf(mx0, fmaxf(S[j][0], S[j][1]));
            mx1 = fmaxf(mx1, fmaxf(S[j][2], S[j][3]));
        }
        mx0 = fmaxf(mx0, __shfl_xor_sync(0xffffffffu, mx0, 1));
        mx0 = fmaxf(mx0, __shfl_xor_sync(0xffffffffu, mx0, 2));
        mx1 = fmaxf(mx1, __shfl_xor_sync(0xffffffffu, mx1, 1));
        mx1 = fmaxf(mx1, __shfl_xor_sync(0xffffffffu, mx1, 2));
        const float mn0 = fmaxf(m0, mx0), mn1 = fmaxf(m1, mx1);
        const float a0 = __expf(m0 - mn0), a1 = __expf(m1 - mn1);
        m0 = mn0; m1 = mn1;
        float s0 = 0.0f, s1 = 0.0f;
#pragma unroll
        for (int j = 0; j < 8; j++) {
            S[j][0] = __expf(S[j][0] - mn0); S[j][1] = __expf(S[j][1] - mn0);
            S[j][2] = __expf(S[j][2] - mn1); S[j][3] = __expf(S[j][3] - mn1);
            s0 += S[j][0] + S[j][1];
            s1 += S[j][2] + S[j][3];
        }
        s0 += __shfl_xor_sync(0xffffffffu, s0, 1);
        s0 += __shfl_xor_sync(0xffffffffu, s0, 2);
        s1 += __shfl_xor_sync(0xffffffffu, s1, 1);
        s1 += __shfl_xor_sync(0xffffffffu, s1, 2);
        l0 = l0 * a0 + s0; l1 = l1 * a1 + s1;
#pragma unroll
        for (int j = 0; j < 8; j++) {
            O[j][0] *= a0; O[j][1] *= a0; O[j][2] *= a1; O[j][3] *= a1;
        }

        // ---- O += P V (3-term, term-major: distance-2 chains) ----
#pragma unroll
        for (int kc = 0; kc < 4; kc++) {
            uint32_t ph[4], pl[4];
#pragma unroll
            for (int half = 0; half < 2; half++) {
                const int j = 2 * kc + half;
                float x0 = S[j][0], x1 = S[j][1], x2 = S[j][2], x3 = S[j][3];
                uint32_t hp = pack_bf16(x0, x1);
                uint32_t hq = pack_bf16(x2, x3);
                ph[half * 2 + 0] = hp;
                ph[half * 2 + 1] = hq;
                __nv_bfloat162 hp2 = *(__nv_bfloat162*)&hp;
                __nv_bfloat162 hq2 = *(__nv_bfloat162*)&hq;
                pl[half * 2 + 0] = pack_bf16(x0 - __bfloat162float(__low2bfloat16(hp2)),
                                             x1 - __bfloat162float(__high2bfloat16(hp2)));
                pl[half * 2 + 1] = pack_bf16(x2 - __bfloat162float(__low2bfloat16(hq2)),
                                             x3 - __bfloat162float(__high2bfloat16(hq2)));
            }
#pragma unroll
            for (int jc = 0; jc < 4; jc++) {
                const int row = kc * 16 + rowSel;
                const int chunk = 2 * jc + hiH;
                const uint32_t off = (uint32_t)(row * 128 + ((chunk ^ (row & 7)) * 16));
                uint32_t rvh[4], rvl[4];
                ldsm4t(rvh, kvb + KV_VH + off);
                ldsm4t(rvl, kvb + KV_VL + off);
                uint32_t v0h[2] = {rvh[0], rvh[1]}, v1h[2] = {rvh[2], rvh[3]};
                uint32_t v0l[2] = {rvl[0], rvl[1]}, v1l[2] = {rvl[2], rvl[3]};
                mma16816(O[2 * jc],     ph, v0h);
                mma16816(O[2 * jc + 1], ph, v1h);
                mma16816(O[2 * jc],     ph, v0l);
                mma16816(O[2 * jc + 1], ph, v1l);
                mma16816(O[2 * jc],     pl, v0h);
                mma16816(O[2 * jc + 1], pl, v1h);
            }
        }
    }

    // ---- epilogue ----
    const float inv0 = 1.0f / l0, inv1 = 1.0f / l1;
    const size_t r0o = (size_t)(b * NN + q0 + qr) * CC;
    const size_t r1o = r0o + (size_t)8 * CC;
    const int cb = h * DH + (lane & 3) * 2;
#pragma unroll
    for (int dj = 0; dj < 8; dj++) {
        const int col = cb + dj * 8;
        split_store(ctxh, ctxl, r0o + col, O[dj][0] * inv0, O[dj][1] * inv0);
        split_store(ctxh, ctxl, r1o + col, O[dj][2] * inv1, O[dj][3] * inv1);
    }
}

// ---------------------------------------------------------------------------
extern "C" void kernel_launch(void* const* d_in, const int* in_sizes, int n_in,
                              void* d_out, int out_size)
{
    (void)in_sizes; (void)n_in; (void)out_size;
    const float* x     = (const float*)d_in[0];
    const float* Wq    = (const float*)d_in[1];
    const float* Wk    = (const float*)d_in[2];
    const float* Wv    = (const float*)d_in[3];
    const float* Wproj = (const float*)d_in[4];
    const float* bproj = (const float*)d_in[5];
    const float* Wpre  = (const float*)d_in[6];
    const float* bpre  = (const float*)d_in[7];
    const float* pi    = (const float*)d_in[8];
    float* out = (float*)d_out;

    float* lgp;
    __nv_bfloat16 *xh, *xl, *preh, *prel, *ctxh, *ctxl;
    __nv_bfloat16 *qhp, *qlp, *khp, *klp, *vhp, *vlp;
    __nv_bfloat16 *wpreh, *wprel, *wqh, *wql, *wkh, *wkl, *wvh, *wvl, *wph, *wpl;
    cudaGetSymbolAddress((void**)&lgp,   g_logits);
    cudaGetSymbolAddress((void**)&xh,    g_xh);
    cudaGetSymbolAddress((void**)&xl,    g_xl);
    cudaGetSymbolAddress((void**)&preh,  g_preh);
    cudaGetSymbolAddress((void**)&prel,  g_prel);
    cudaGetSymbolAddress((void**)&ctxh,  g_ctxh);
    cudaGetSymbolAddress((void**)&ctxl,  g_ctxl);
    cudaGetSymbolAddress((void**)&qhp,   g_qh);
    cudaGetSymbolAddress((void**)&qlp,   g_ql);
    cudaGetSymbolAddress((void**)&khp,   g_kh);
    cudaGetSymbolAddress((void**)&klp,   g_kl);
    cudaGetSymbolAddress((void**)&vhp,   g_vh);
    cudaGetSymbolAddress((void**)&vlp,   g_vl);
    cudaGetSymbolAddress((void**)&wpreh, g_wpreh);
    cudaGetSymbolAddress((void**)&wprel, g_wprel);
    cudaGetSymbolAddress((void**)&wqh,   g_wqh);
    cudaGetSymbolAddress((void**)&wql,   g_wql);
    cudaGetSymbolAddress((void**)&wkh,   g_wkh);
    cudaGetSymbolAddress((void**)&wkl,   g_wkl);
    cudaGetSymbolAddress((void**)&wvh,   g_wvh);
    cudaGetSymbolAddress((void**)&wvl,   g_wvl);
    cudaGetSymbolAddress((void**)&wph,   g_wph);
    cudaGetSymbolAddress((void**)&wpl,   g_wpl);

    cudaFuncSetAttribute(hmma_qkv,  cudaFuncAttributeMaxDynamicSharedMemorySize, SMEM_HMMA);
    cudaFuncSetAttribute(hmma_gemm, cudaFuncAttributeMaxDynamicSharedMemorySize, SMEM_HMMA);
    cudaFuncSetAttribute(fattn,     cudaFuncAttributeMaxDynamicSharedMemorySize, SMEM_FATT);

    // ---- prep ----
    dim3 wst(32, 8), wsg(32, 32, 5);
    wsplit_T5<<<wsg, wst>>>(Wpre, Wq, Wk, Wv, Wproj,
                            wpreh, wprel, wqh, wql, wkh, wkl, wvh, wvl, wph, wpl);
    const int n2 = MROWS * CC / 2;
    split2<<<(n2 + 255) / 256, 256>>>((const float2*)x,
        (__nv_bfloat162*)xh, (__nv_bfloat162*)xl, n2);

    // ---- merged pre/Q/K/V GEMM ----
    dim3 mb(256);
    dim3 gqkv(32, MROWS / 128, 1);
    hmma_qkv<<<gqkv, mb, SMEM_HMMA>>>(xh, xl,
        wpreh, wprel, wqh, wql, wkh, wkl, wvh, wvl, bpre,
        preh, prel, qhp, qlp, khp, klp, vhp, vlp);

    // ---- logits GEMM (symmetric: 36 upper-tri tiles/batch) ----
    dim3 glog(36, 1, BB);
    hmma_gemm<<<glog, mb, SMEM_HMMA>>>(preh, prel, preh, prel, nullptr, nullptr,
                                       lgp, EPI_LOGITS,
                                       (long long)NN * CC, (long long)NN * CC);

    // ---- HMMA flash attention ----
    dim3 ga(NN / 128, BB * HH);
    fattn<<<ga, 256, SMEM_FATT>>>(qhp, qlp, khp, klp, vhp, vlp, lgp, pi,
                                  ctxh, ctxl);

    // ---- projection + residual ----
    dim3 gl(CC / 128, MROWS / 128, 1);
    hmma_gemm<<<gl, mb, SMEM_HMMA>>>(ctxh, ctxl, wph, wpl, bproj, x,
                                     out, EPI_RESID, 0, 0);
}

// round 11
// speedup vs baseline: 1.6219x; 1.3588x over previous
#include <cuda_runtime.h>
#include <cuda_fp16.h>
#include <math.h>
#include <stdint.h>

#define BB 4
#define NN 1024
#define CC 1024
#define HH 16
#define DH 64
#define MROWS (BB*NN)   // 4096

// ---------------- scratch (device globals; no allocation allowed) ----------
__device__ float g_logits[BB*NN*NN];               // 16 MB
__device__ __half g_xh[MROWS*CC];
__device__ __half g_xl[MROWS*CC];
__device__ __half g_preh[MROWS*CC];
__device__ __half g_prel[MROWS*CC];
__device__ __half g_ctxh[MROWS*CC];
__device__ __half g_ctxl[MROWS*CC];
__device__ __half g_qh[BB*HH*NN*DH], g_ql[BB*HH*NN*DH];
__device__ __half g_kh[BB*HH*NN*DH];
__device__ __half g_vh[BB*HH*NN*DH], g_vl[BB*HH*NN*DH];
__device__ __half g_wpre[CC*CC];
__device__ __half g_wq[CC*CC];
__device__ __half g_wk[CC*CC];
__device__ __half g_wv[CC*CC];
__device__ __half g_wp[CC*CC];

// ======================= portable PTX helpers ==============================
__device__ __forceinline__ uint32_t smem_to_u32(const void* p) {
    uint32_t a;
    asm("{ .reg .u64 t; cvta.to.shared.u64 t, %1; cvt.u32.u64 %0, t; }"
        : "=r"(a) : "l"(p));
    return a;
}
#define CP_ASYNC16(dst, src) \
    asm volatile("cp.async.cg.shared.global [%0], [%1], 16;" \
                 :: "r"(dst), "l"(src) : "memory")
#define CP_COMMIT() asm volatile("cp.async.commit_group;" ::: "memory")
#define CP_WAIT0()  asm volatile("cp.async.wait_group 0;" ::: "memory")

__device__ __forceinline__ void ldsm4(uint32_t* r, uint32_t addr) {
    asm volatile("ldmatrix.sync.aligned.m8n8.x4.shared.b16 {%0,%1,%2,%3}, [%4];"
        : "=r"(r[0]), "=r"(r[1]), "=r"(r[2]), "=r"(r[3]) : "r"(addr));
}
__device__ __forceinline__ void ldsm4t(uint32_t* r, uint32_t addr) {
    asm volatile("ldmatrix.sync.aligned.m8n8.x4.trans.shared.b16 {%0,%1,%2,%3}, [%4];"
        : "=r"(r[0]), "=r"(r[1]), "=r"(r[2]), "=r"(r[3]) : "r"(addr));
}
// fp16 MMA with fp32 accumulate
__device__ __forceinline__ void mma16816(float* c, const uint32_t* a,
                                         const uint32_t* b) {
    asm volatile("mma.sync.aligned.m16n8k16.row.col.f32.f16.f16.f32 "
        "{%0,%1,%2,%3}, {%4,%5,%6,%7}, {%8,%9}, {%0,%1,%2,%3};"
        : "+f"(c[0]), "+f"(c[1]), "+f"(c[2]), "+f"(c[3])
        : "r"(a[0]), "r"(a[1]), "r"(a[2]), "r"(a[3]), "r"(b[0]), "r"(b[1]));
}
__device__ __forceinline__ uint32_t pack_h2(float x, float y) {
    __half2 p = __floats2half2_rn(x, y);
    return *(uint32_t*)&p;
}

// ======================= prep kernels ======================================
__global__ __launch_bounds__(256) void split2h(
    const float2* __restrict__ in, __half2* __restrict__ hi,
    __half2* __restrict__ lo, int n2)
{
    int i = blockIdx.x * blockDim.x + threadIdx.x;
    if (i < n2) {
        float2 a = in[i];
        __half hx = __float2half(a.x), hy = __float2half(a.y);
        float lx = a.x - __half2float(hx), ly = a.y - __half2float(hy);
        hi[i] = __halves2half2(hx, hy);
        lo[i] = __halves2half2(__float2half(lx), __float2half(ly));
    }
}

// 5 weights: W[K,C] fp32 -> Wt[C,K] fp16 (transpose + round, single output)
__global__ __launch_bounds__(256) void wround_T5(
    const float* __restrict__ W0, const float* __restrict__ W1,
    const float* __restrict__ W2, const float* __restrict__ W3,
    const float* __restrict__ W4,
    __half* o0, __half* o1, __half* o2, __half* o3, __half* o4)
{
    const float* Ws[5] = {W0, W1, W2, W3, W4};
    __half* Os[5] = {o0, o1, o2, o3, o4};
    const int z = blockIdx.z;
    const float* W = Ws[z];
    __half* th = Os[z];

    __shared__ float s[32][33];
    const int tx = threadIdx.x, ty = threadIdx.y;
    const int n0 = blockIdx.x * 32, k0 = blockIdx.y * 32;
#pragma unroll
    for (int i = ty; i < 32; i += 8)
        s[i][tx] = W[(size_t)(k0 + i) * CC + n0 + tx];
    __syncthreads();
#pragma unroll
    for (int i = ty; i < 32; i += 8)
        th[(size_t)(n0 + i) * CC + k0 + tx] = __float2half(s[tx][i]);
}

// ======================= HMMA GEMM common machinery ========================
// fp16 one-side split: C = (Ah + Al) . B^T, B rounded fp16. 2 MMA terms.
enum { EPI_PRE = 0, EPI_BHND = 1, EPI_LOGITS = 2, EPI_RESID = 3 };

#define OFF_AH 0
#define OFF_AL 8192
#define OFF_B  16384
#define STAGE_BYTES 24576
#define SMEM_HMMA (2 * STAGE_BYTES)    // 49152

struct GemmCore {
    uint32_t smem_u32;
    int lane, wid, wr, wc, lrow, lc, rowSel, hiH, rmod;
    __device__ __forceinline__ void init(uint32_t smem, int t) {
        smem_u32 = smem;
        lane = t & 31; wid = t >> 5;
        wr = wid & 1; wc = wid >> 1;
        lrow = t >> 2; lc = t & 3;
        rowSel = lane & 15; hiH = lane >> 4; rmod = (rowSel >> 1) & 3;
    }
    __device__ __forceinline__ void load_stage(
        const __half* Ahb, const __half* Alb, const __half* Bb,
        int row0, int col0, int ch, int s) const
    {
        const size_t kb = (size_t)ch * 32 + lc * 8;
        const uint32_t sb = smem_u32 + s * STAGE_BYTES;
#pragma unroll
        for (int i = 0; i < 2; i++) {
            const int r = lrow + i * 64;
            const uint32_t so = (uint32_t)(r * 64 + ((lc ^ ((r >> 1) & 3)) * 16));
            const size_t ga = (size_t)(row0 + r) * CC + kb;
            const size_t gb = (size_t)(col0 + r) * CC + kb;
            CP_ASYNC16(sb + OFF_AH + so, Ahb + ga);
            CP_ASYNC16(sb + OFF_AL + so, Alb + ga);
            CP_ASYNC16(sb + OFF_B  + so, Bb  + gb);
        }
    }
    __device__ __forceinline__ void run(
        const __half* Ahb, const __half* Alb, const __half* Bb,
        int row0, int col0, float acc[4][4][4]) const
    {
#pragma unroll
        for (int a = 0; a < 4; a++)
#pragma unroll
            for (int b = 0; b < 4; b++)
#pragma unroll
                for (int c = 0; c < 4; c++) acc[a][b][c] = 0.0f;

        load_stage(Ahb, Alb, Bb, row0, col0, 0, 0);
        CP_COMMIT();
        for (int ch = 0; ch < 32; ch++) {
            CP_WAIT0();
            __syncthreads();
            if (ch < 31) {
                load_stage(Ahb, Alb, Bb, row0, col0, ch + 1, (ch + 1) & 1);
                CP_COMMIT();
            }

            const uint32_t sb = smem_u32 + (ch & 1) * STAGE_BYTES;
#pragma unroll
            for (int k16 = 0; k16 < 2; k16++) {
                const int chunk = k16 * 2 + hiH;
                uint32_t bh[4][2];
#pragma unroll
                for (int n16 = 0; n16 < 2; n16++) {
                    const int row = wc * 32 + n16 * 16 + rowSel;
                    const uint32_t off = (uint32_t)(row * 64 + ((chunk ^ rmod) * 16));
                    uint32_t rh[4];
                    ldsm4(rh, sb + OFF_B + off);
                    bh[n16 * 2][0] = rh[0]; bh[n16 * 2 + 1][0] = rh[1];
                    bh[n16 * 2][1] = rh[2]; bh[n16 * 2 + 1][1] = rh[3];
                }
#pragma unroll
                for (int mt = 0; mt < 4; mt++) {
                    const int row = wr * 64 + mt * 16 + rowSel;
                    const uint32_t off = (uint32_t)(row * 64 + ((chunk ^ rmod) * 16));
                    uint32_t ah[4], al[4];
                    ldsm4(ah, sb + OFF_AH + off);
                    ldsm4(al, sb + OFF_AL + off);
#pragma unroll
                    for (int nt = 0; nt < 4; nt++) mma16816(acc[mt][nt], ah, bh[nt]);
#pragma unroll
                    for (int nt = 0; nt < 4; nt++) mma16816(acc[mt][nt], al, bh[nt]);
                }
            }
        }
    }
};

__device__ __forceinline__ void split_store_h(__half* oh, __half* ol,
                                              size_t off, float v0, float v1) {
    __half h0 = __float2half(v0);
    __half h1 = __float2half(v1);
    *(__half2*)(oh + off) = __halves2half2(h0, h1);
    *(__half2*)(ol + off) = __halves2half2(
        __float2half(v0 - __half2float(h0)),
        __float2half(v1 - __half2float(h1)));
}

// ---- merged pre/Q/K/V GEMM ------------------------------------------------
__global__ __launch_bounds__(256) void hmma_qkv(
    const __half* __restrict__ xh, const __half* __restrict__ xl,
    const __half* wpre, const __half* wq, const __half* wk, const __half* wv,
    const float* __restrict__ bpre,
    __half* preh, __half* prel,
    __half* qh, __half* ql, __half* kh, __half* vh, __half* vl)
{
    extern __shared__ char smem_raw[];
    GemmCore gc_;
    gc_.init(smem_to_u32(smem_raw), threadIdx.x);

    const int g    = blockIdx.x >> 3;
    const int col0 = (blockIdx.x & 7) * 128;
    const int row0 = blockIdx.y * 128;

    const __half* Bp[4] = {wpre, wq, wk, wv};

    float acc[4][4][4];
    gc_.run(xh, xl, Bp[g], row0, col0, acc);

    const int r0g = row0 + gc_.wr * 64 + (gc_.lane >> 2);
    const int c0g = col0 + gc_.wc * 32 + (gc_.lane & 3) * 2;
#pragma unroll
    for (int mt = 0; mt < 4; mt++) {
#pragma unroll
        for (int nt = 0; nt < 4; nt++) {
            const int gcc = c0g + nt * 8;
#pragma unroll
            for (int half = 0; half < 2; half++) {
                const int gr = r0g + mt * 16 + half * 8;
                float v0 = acc[mt][nt][half * 2 + 0];
                float v1 = acc[mt][nt][half * 2 + 1];
                if (g == 0) {
                    v0 += bpre[gcc]; v1 += bpre[gcc + 1];
                    v0 = v0 / (1.0f + __expf(-v0));
                    v1 = v1 / (1.0f + __expf(-v1));
                    split_store_h(preh, prel, (size_t)gr * CC + gcc, v0, v1);
                } else {
                    const int b = gr >> 10, n = gr & (NN - 1);
                    const int h = gcc >> 6, dh = gcc & 63;
                    const size_t o = ((size_t)(b * HH + h) * NN + n) * DH + dh;
                    if (g == 1)      split_store_h(qh, ql, o, v0, v1);
                    else if (g == 2) // K rounded single
                        *(__half2*)(kh + o) = __floats2half2_rn(v0, v1);
                    else             split_store_h(vh, vl, o, v0, v1);
                }
            }
        }
    }
}

// ---- logits (symmetric, upper-tri tiles) + proj/resid GEMM ----------------
__global__ __launch_bounds__(256) void hmma_gemm(
    const __half* __restrict__ Ah, const __half* __restrict__ Al,
    const __half* __restrict__ Bs,
    const float* __restrict__ bias, const float* __restrict__ resid,
    float* __restrict__ outF, int mode, long long bsA, long long bsB)
{
    extern __shared__ char smem_raw[];
    GemmCore gc_;
    gc_.init(smem_to_u32(smem_raw), threadIdx.x);

    int row0, col0, ti = 0, tj = 0;
    if (mode == EPI_LOGITS) {
        int li = blockIdx.x, rem = 8;
        while (li >= rem) { li -= rem; rem--; ti++; }
        tj = ti + li;
        row0 = ti * 128; col0 = tj * 128;
    } else {
        row0 = blockIdx.y * 128;
        col0 = blockIdx.x * 128;
    }
    const int z = blockIdx.z;
    const __half* Ahb = Ah + (size_t)z * bsA;
    const __half* Alb = Al + (size_t)z * bsA;
    const __half* Bb  = Bs + (size_t)z * bsB;

    float acc[4][4][4];
    gc_.run(Ahb, Alb, Bb, row0, col0, acc);

    const int r0g = row0 + gc_.wr * 64 + (gc_.lane >> 2);
    const int c0g = col0 + gc_.wc * 32 + (gc_.lane & 3) * 2;
#pragma unroll
    for (int mt = 0; mt < 4; mt++) {
#pragma unroll
        for (int nt = 0; nt < 4; nt++) {
            const int gcc = c0g + nt * 8;
#pragma unroll
            for (int half = 0; half < 2; half++) {
                const int gr = r0g + mt * 16 + half * 8;
                float v0 = acc[mt][nt][half * 2 + 0];
                float v1 = acc[mt][nt][half * 2 + 1];
                if (mode == EPI_LOGITS) {
                    float* base = outF + (size_t)z * NN * NN;
                    v0 *= 0.03125f; v1 *= 0.03125f;
                    base[(size_t)gr * NN + gcc]     = v0;
                    base[(size_t)gr * NN + gcc + 1] = v1;
                    if (ti != tj) {
                        base[(size_t)gcc * NN + gr]       = v0;
                        base[(size_t)(gcc + 1) * NN + gr] = v1;
                    }
                } else { // EPI_RESID
                    const size_t ro = (size_t)gr * CC + gcc;
                    outF[ro]     = v0 + bias[gcc]     + resid[ro];
                    outF[ro + 1] = v1 + bias[gcc + 1] + resid[ro + 1];
                }
            }
        }
    }
}

// ======================= HMMA flash attention (128-q tile) =================
// Q split fp16 (resident 32KB) + double-buffered K(single)/V(split): stage 24KB.
#define SMQ_H 0
#define SMQ_L 16384
#define KVBASE 32768
#define KVST 24576
#define KV_K  0
#define KV_VH 8192
#define KV_VL 16384
#define SMEM_FATT (KVBASE + 2 * KVST)    // 81920

__global__ __launch_bounds__(256, 2) void fattn(
    const __half* __restrict__ qh, const __half* __restrict__ ql,
    const __half* __restrict__ kh,
    const __half* __restrict__ vh, const __half* __restrict__ vl,
    const float* __restrict__ logits, const float* __restrict__ pi_p,
    __half* __restrict__ ctxh, __half* __restrict__ ctxl)
{
    extern __shared__ char sm[];
    const uint32_t sb = smem_to_u32(sm);
    const int t = threadIdx.x, lane = t & 31, w = t >> 5;
    const int bh = blockIdx.y, b = bh >> 4, h = bh & 15;
    const int q0 = blockIdx.x * 128;
    const size_t hoff = (size_t)bh * NN * DH;
    const float pi = pi_p[0];

    // Q async load (once)
#pragma unroll
    for (int i = 0; i < 4; i++) {
        const int id = t + i * 256;
        const int r = id >> 3, c = id & 7;
        const uint32_t off = (uint32_t)(r * 128 + ((c ^ (r & 7)) * 16));
        const size_t g = hoff + (size_t)(q0 + r) * DH + c * 8;
        CP_ASYNC16(sb + SMQ_H + off, qh + g);
        CP_ASYNC16(sb + SMQ_L + off, ql + g);
    }
    CP_COMMIT();

    auto load_kv = [&](int kt, int buf) {
        const uint32_t kvb = sb + KVBASE + buf * KVST;
#pragma unroll
        for (int i = 0; i < 2; i++) {
            const int id = t + i * 256;
            const int r = id >> 3, c = id & 7;
            const uint32_t off = (uint32_t)(r * 128 + ((c ^ (r & 7)) * 16));
            const size_t g = hoff + (size_t)(kt * 64 + r) * DH + c * 8;
            CP_ASYNC16(kvb + KV_K  + off, kh + g);
            CP_ASYNC16(kvb + KV_VH + off, vh + g);
            CP_ASYNC16(kvb + KV_VL + off, vl + g);
        }
    };

    load_kv(0, 0);
    CP_COMMIT();

    float S[8][4], O[8][4];
#pragma unroll
    for (int j = 0; j < 8; j++)
#pragma unroll
        for (int c = 0; c < 4; c++) O[j][c] = 0.0f;
    float m0 = -1e30f, m1 = -1e30f, l0 = 0.0f, l1 = 0.0f;

    const int qr = w * 16 + (lane >> 2);
    const float* lgr = logits + (size_t)b * NN * NN + (size_t)(q0 + qr) * NN;
    const int rowSel = lane & 15, hiH = lane >> 4;

    for (int kt = 0; kt < 16; kt++) {
        const int mk = kt * 64;
        CP_WAIT0();
        __syncthreads();
        if (kt < 15) { load_kv(kt + 1, (kt + 1) & 1); CP_COMMIT(); }

        const uint32_t kvb = sb + KVBASE + (kt & 1) * KVST;

        // ---- S = (Qh+Ql) K^T (2-term) ----
#pragma unroll
        for (int j = 0; j < 8; j++)
#pragma unroll
            for (int c = 0; c < 4; c++) S[j][c] = 0.0f;

#pragma unroll
        for (int kc = 0; kc < 4; kc++) {
            const int chunk = 2 * kc + hiH;
            uint32_t aqh[4], aql[4];
            {
                const int row = w * 16 + rowSel;
                const uint32_t off = (uint32_t)(row * 128 + ((chunk ^ (row & 7)) * 16));
                ldsm4(aqh, sb + SMQ_H + off);
                ldsm4(aql, sb + SMQ_L + off);
            }
#pragma unroll
            for (int j16 = 0; j16 < 4; j16++) {
                const int row = j16 * 16 + rowSel;
                const uint32_t off = (uint32_t)(row * 128 + ((chunk ^ (row & 7)) * 16));
                uint32_t rh[4];
                ldsm4(rh, kvb + KV_K + off);
                uint32_t b0h[2] = {rh[0], rh[2]}, b1h[2] = {rh[1], rh[3]};
                mma16816(S[2 * j16],     aqh, b0h);
                mma16816(S[2 * j16 + 1], aqh, b1h);
                mma16816(S[2 * j16],     aql, b0h);
                mma16816(S[2 * j16 + 1], aql, b1h);
            }
        }

        // ---- bias + online softmax ----
        float mx0 = -1e30f, mx1 = -1e30f;
#pragma unroll
        for (int j = 0; j < 8; j++) {
            const float2 L0 = *(const float2*)(lgr + mk + j * 8 + (lane & 3) * 2);
            const float2 L1 = *(const float2*)(lgr + 8 * NN + mk + j * 8 + (lane & 3) * 2);
            S[j][0] = S[j][0] * 0.125f + pi * L0.x;
            S[j][1] = S[j][1] * 0.125f + pi * L0.y;
            S[j][2] = S[j][2] * 0.125f + pi * L1.x;
            S[j][3] = S[j][3] * 0.125f + pi * L1.y;
            mx0 = fmaxf(mx0, fmaxf(S[j][0], S[j][1]));
            mx1 = fmaxf(mx1, fmaxf(S[j][2], S[j][3]));
        }
        mx0 = fmaxf(mx0, __shfl_xor_sync(0xffffffffu, mx0, 1));
        mx0 = fmaxf(mx0, __shfl_xor_sync(0xffffffffu, mx0, 2));
        mx1 = fmaxf(mx1, __shfl_xor_sync(0xffffffffu, mx1, 1));
        mx1 = fmaxf(mx1, __shfl_xor_sync(0xffffffffu, mx1, 2));
        const float mn0 = fmaxf(m0, mx0), mn1 = fmaxf(m1, mx1);
        const float a0 = __expf(m0 - mn0), a1 = __expf(m1 - mn1);
        m0 = mn0; m1 = mn1;
        float s0 = 0.0f, s1 = 0.0f;
#pragma unroll
        for (int j = 0; j < 8; j++) {
            S[j][0] = __expf(S[j][0] - mn0); S[j][1] = __expf(S[j][1] - mn0);
            S[j][2] = __expf(S[j][2] - mn1); S[j][3] = __expf(S[j][3] - mn1);
            s0 += S[j][0] + S[j][1];
            s1 += S[j][2] + S[j][3];
        }
        s0 += __shfl_xor_sync(0xffffffffu, s0, 1);
        s0 += __shfl_xor_sync(0xffffffffu, s0, 2);
        s1 += __shfl_xor_sync(0xffffffffu, s1, 1);
        s1 += __shfl_xor_sync(0xffffffffu, s1, 2);
        l0 = l0 * a0 + s0; l1 = l1 * a1 + s1;
#pragma unroll
        for (int j = 0; j < 8; j++) {
            O[j][0] *= a0; O[j][1] *= a0; O[j][2] *= a1; O[j][3] *= a1;
        }

        // ---- O += P (Vh+Vl), P rounded single fp16 (2-term) ----
#pragma unroll
        for (int kc = 0; kc < 4; kc++) {
            uint32_t ph[4];
#pragma unroll
            for (int half = 0; half < 2; half++) {
                const int j = 2 * kc + half;
                ph[half * 2 + 0] = pack_h2(S[j][0], S[j][1]);
                ph[half * 2 + 1] = pack_h2(S[j][2], S[j][3]);
            }
#pragma unroll
            for (int jc = 0; jc < 4; jc++) {
                const int row = kc * 16 + rowSel;
                const int chunk = 2 * jc + hiH;
                const uint32_t off = (uint32_t)(row * 128 + ((chunk ^ (row & 7)) * 16));
                uint32_t rvh[4], rvl[4];
                ldsm4t(rvh, kvb + KV_VH + off);
                ldsm4t(rvl, kvb + KV_VL + off);
                uint32_t v0h[2] = {rvh[0], rvh[1]}, v1h[2] = {rvh[2], rvh[3]};
                uint32_t v0l[2] = {rvl[0], rvl[1]}, v1l[2] = {rvl[2], rvl[3]};
                mma16816(O[2 * jc],     ph, v0h);
                mma16816(O[2 * jc + 1], ph, v1h);
                mma16816(O[2 * jc],     ph, v0l);
                mma16816(O[2 * jc + 1], ph, v1l);
            }
        }
    }

    // ---- epilogue ----
    const float inv0 = 1.0f / l0, inv1 = 1.0f / l1;
    const size_t r0o = (size_t)(b * NN + q0 + qr) * CC;
    const size_t r1o = r0o + (size_t)8 * CC;
    const int cb = h * DH + (lane & 3) * 2;
#pragma unroll
    for (int dj = 0; dj < 8; dj++) {
        const int col = cb + dj * 8;
        split_store_h(ctxh, ctxl, r0o + col, O[dj][0] * inv0, O[dj][1] * inv0);
        split_store_h(ctxh, ctxl, r1o + col, O[dj][2] * inv1, O[dj][3] * inv1);
    }
}

// ---------------------------------------------------------------------------
extern "C" void kernel_launch(void* const* d_in, const int* in_sizes, int n_in,
                              void* d_out, int out_size)
{
    (void)in_sizes; (void)n_in; (void)out_size;
    const float* x     = (const float*)d_in[0];
    const float* Wq    = (const float*)d_in[1];
    const float* Wk    = (const float*)d_in[2];
    const float* Wv    = (const float*)d_in[3];
    const float* Wproj = (const float*)d_in[4];
    const float* bproj = (const float*)d_in[5];
    const float* Wpre  = (const float*)d_in[6];
    const float* bpre  = (const float*)d_in[7];
    const float* pi    = (const float*)d_in[8];
    float* out = (float*)d_out;

    float* lgp;
    __half *xh, *xl, *preh, *prel, *ctxh, *ctxl;
    __half *qhp, *qlp, *khp, *vhp, *vlp;
    __half *wpre, *wq, *wk, *wv, *wp;
    cudaGetSymbolAddress((void**)&lgp,  g_logits);
    cudaGetSymbolAddress((void**)&xh,   g_xh);
    cudaGetSymbolAddress((void**)&xl,   g_xl);
    cudaGetSymbolAddress((void**)&preh, g_preh);
    cudaGetSymbolAddress((void**)&prel, g_prel);
    cudaGetSymbolAddress((void**)&ctxh, g_ctxh);
    cudaGetSymbolAddress((void**)&ctxl, g_ctxl);
    cudaGetSymbolAddress((void**)&qhp,  g_qh);
    cudaGetSymbolAddress((void**)&qlp,  g_ql);
    cudaGetSymbolAddress((void**)&khp,  g_kh);
    cudaGetSymbolAddress((void**)&vhp,  g_vh);
    cudaGetSymbolAddress((void**)&vlp,  g_vl);
    cudaGetSymbolAddress((void**)&wpre, g_wpre);
    cudaGetSymbolAddress((void**)&wq,   g_wq);
    cudaGetSymbolAddress((void**)&wk,   g_wk);
    cudaGetSymbolAddress((void**)&wv,   g_wv);
    cudaGetSymbolAddress((void**)&wp,   g_wp);

    cudaFuncSetAttribute(hmma_qkv,  cudaFuncAttributeMaxDynamicSharedMemorySize, SMEM_HMMA);
    cudaFuncSetAttribute(hmma_gemm, cudaFuncAttributeMaxDynamicSharedMemorySize, SMEM_HMMA);
    cudaFuncSetAttribute(fattn,     cudaFuncAttributeMaxDynamicSharedMemorySize, SMEM_FATT);

    // ---- prep ----
    dim3 wst(32, 8), wsg(32, 32, 5);
    wround_T5<<<wsg, wst>>>(Wpre, Wq, Wk, Wv, Wproj, wpre, wq, wk, wv, wp);
    const int n2 = MROWS * CC / 2;
    split2h<<<(n2 + 255) / 256, 256>>>((const float2*)x,
        (__half2*)xh, (__half2*)xl, n2);

    // ---- merged pre/Q/K/V GEMM ----
    dim3 mb(256);
    dim3 gqkv(32, MROWS / 128, 1);
    hmma_qkv<<<gqkv, mb, SMEM_HMMA>>>(xh, xl, wpre, wq, wk, wv, bpre,
                                      preh, prel, qhp, qlp, khp, vhp, vlp);

    // ---- logits GEMM (symmetric: 36 upper-tri tiles/batch) ----
    // A = pre split (h+l), B = preh (the rounded-single value).
    dim3 glog(36, 1, BB);
    hmma_gemm<<<glog, mb, SMEM_HMMA>>>(preh, prel, preh, nullptr, nullptr,
                                       lgp, EPI_LOGITS,
                                       (long long)NN * CC, (long long)NN * CC);

    // ---- HMMA flash attention ----
    dim3 ga(NN / 128, BB * HH);
    fattn<<<ga, 256, SMEM_FATT>>>(qhp, qlp, khp, vhp, vlp, lgp, pi,
                                  ctxh, ctxl);

    // ---- projection + residual ----
    dim3 gl(CC / 128, MROWS / 128, 1);
    hmma_gemm<<<gl, mb, SMEM_HMMA>>>(ctxh, ctxl, wp, bproj, x,
                                     out, EPI_RESID, 0, 0);
}

// round 12
// speedup vs baseline: 2.4958x; 1.5388x over previous
#include <cuda_runtime.h>
#include <cuda_fp16.h>
#include <math.h>
#include <stdint.h>

#define BB 4
#define NN 1024
#define CC 1024
#define HH 16
#define DH 64
#define MROWS (BB*NN)   // 4096

// ---------------- scratch (device globals; no allocation allowed) ----------
__device__ float g_logits[BB*NN*NN];               // 16 MB
__device__ __half g_x16[MROWS*CC];
__device__ __half g_pre[MROWS*CC];
__device__ __half g_ctx[MROWS*CC];
__device__ __half g_q16[BB*HH*NN*DH];
__device__ __half g_k16[BB*HH*NN*DH];
__device__ __half g_v16[BB*HH*NN*DH];
__device__ __half g_wpre[CC*CC];
__device__ __half g_wq[CC*CC];
__device__ __half g_wk[CC*CC];
__device__ __half g_wv[CC*CC];
__device__ __half g_wp[CC*CC];

// ======================= portable PTX helpers ==============================
__device__ __forceinline__ uint32_t smem_to_u32(const void* p) {
    uint32_t a;
    asm("{ .reg .u64 t; cvta.to.shared.u64 t, %1; cvt.u32.u64 %0, t; }"
        : "=r"(a) : "l"(p));
    return a;
}
#define CP_ASYNC16(dst, src) \
    asm volatile("cp.async.cg.shared.global [%0], [%1], 16;" \
                 :: "r"(dst), "l"(src) : "memory")
#define CP_COMMIT() asm volatile("cp.async.commit_group;" ::: "memory")
#define CP_WAIT0()  asm volatile("cp.async.wait_group 0;" ::: "memory")

__device__ __forceinline__ void ldsm4(uint32_t* r, uint32_t addr) {
    asm volatile("ldmatrix.sync.aligned.m8n8.x4.shared.b16 {%0,%1,%2,%3}, [%4];"
        : "=r"(r[0]), "=r"(r[1]), "=r"(r[2]), "=r"(r[3]) : "r"(addr));
}
__device__ __forceinline__ void ldsm4t(uint32_t* r, uint32_t addr) {
    asm volatile("ldmatrix.sync.aligned.m8n8.x4.trans.shared.b16 {%0,%1,%2,%3}, [%4];"
        : "=r"(r[0]), "=r"(r[1]), "=r"(r[2]), "=r"(r[3]) : "r"(addr));
}
__device__ __forceinline__ void mma16816(float* c, const uint32_t* a,
                                         const uint32_t* b) {
    asm volatile("mma.sync.aligned.m16n8k16.row.col.f32.f16.f16.f32 "
        "{%0,%1,%2,%3}, {%4,%5,%6,%7}, {%8,%9}, {%0,%1,%2,%3};"
        : "+f"(c[0]), "+f"(c[1]), "+f"(c[2]), "+f"(c[3])
        : "r"(a[0]), "r"(a[1]), "r"(a[2]), "r"(a[3]), "r"(b[0]), "r"(b[1]));
}
__device__ __forceinline__ uint32_t pack_h2(float x, float y) {
    __half2 p = __floats2half2_rn(x, y);
    return *(uint32_t*)&p;
}

// ======================= prep kernels ======================================
__global__ __launch_bounds__(256) void round2h(
    const float2* __restrict__ in, __half2* __restrict__ o, int n2)
{
    int i = blockIdx.x * blockDim.x + threadIdx.x;
    if (i < n2) {
        float2 a = in[i];
        o[i] = __floats2half2_rn(a.x, a.y);
    }
}

// 5 weights: W[K,C] fp32 -> Wt[C,K] fp16 (transpose + round)
__global__ __launch_bounds__(256) void wround_T5(
    const float* __restrict__ W0, const float* __restrict__ W1,
    const float* __restrict__ W2, const float* __restrict__ W3,
    const float* __restrict__ W4,
    __half* o0, __half* o1, __half* o2, __half* o3, __half* o4)
{
    const float* Ws[5] = {W0, W1, W2, W3, W4};
    __half* Os[5] = {o0, o1, o2, o3, o4};
    const int z = blockIdx.z;
    const float* W = Ws[z];
    __half* th = Os[z];

    __shared__ float s[32][33];
    const int tx = threadIdx.x, ty = threadIdx.y;
    const int n0 = blockIdx.x * 32, k0 = blockIdx.y * 32;
#pragma unroll
    for (int i = ty; i < 32; i += 8)
        s[i][tx] = W[(size_t)(k0 + i) * CC + n0 + tx];
    __syncthreads();
#pragma unroll
    for (int i = ty; i < 32; i += 8)
        th[(size_t)(n0 + i) * CC + k0 + tx] = __float2half(s[tx][i]);
}

// ======================= HMMA GEMM common machinery ========================
// single-fp16 both sides: C = A . B^T, 1 MMA term per k16.
enum { EPI_PRE = 0, EPI_BHND = 1, EPI_LOGITS = 2, EPI_RESID = 3 };

#define OFF_A 0
#define OFF_B 8192
#define STAGE_BYTES 16384
#define SMEM_HMMA (2 * STAGE_BYTES)    // 32768 -> 2 CTAs/SM

struct GemmCore {
    uint32_t smem_u32;
    int lane, wid, wr, wc, lrow, lc, rowSel, hiH, rmod;
    __device__ __forceinline__ void init(uint32_t smem, int t) {
        smem_u32 = smem;
        lane = t & 31; wid = t >> 5;
        wr = wid & 1; wc = wid >> 1;
        lrow = t >> 2; lc = t & 3;
        rowSel = lane & 15; hiH = lane >> 4; rmod = (rowSel >> 1) & 3;
    }
    __device__ __forceinline__ void load_stage(
        const __half* Ab, const __half* Bb,
        int row0, int col0, int ch, int s) const
    {
        const size_t kb = (size_t)ch * 32 + lc * 8;
        const uint32_t sb = smem_u32 + s * STAGE_BYTES;
#pragma unroll
        for (int i = 0; i < 2; i++) {
            const int r = lrow + i * 64;
            const uint32_t so = (uint32_t)(r * 64 + ((lc ^ ((r >> 1) & 3)) * 16));
            CP_ASYNC16(sb + OFF_A + so, Ab + (size_t)(row0 + r) * CC + kb);
            CP_ASYNC16(sb + OFF_B + so, Bb + (size_t)(col0 + r) * CC + kb);
        }
    }
    __device__ __forceinline__ void run(
        const __half* Ab, const __half* Bb,
        int row0, int col0, float acc[4][4][4]) const
    {
#pragma unroll
        for (int a = 0; a < 4; a++)
#pragma unroll
            for (int b = 0; b < 4; b++)
#pragma unroll
                for (int c = 0; c < 4; c++) acc[a][b][c] = 0.0f;

        load_stage(Ab, Bb, row0, col0, 0, 0);
        CP_COMMIT();
        for (int ch = 0; ch < 32; ch++) {
            CP_WAIT0();
            __syncthreads();
            if (ch < 31) {
                load_stage(Ab, Bb, row0, col0, ch + 1, (ch + 1) & 1);
                CP_COMMIT();
            }

            const uint32_t sb = smem_u32 + (ch & 1) * STAGE_BYTES;
#pragma unroll
            for (int k16 = 0; k16 < 2; k16++) {
                const int chunk = k16 * 2 + hiH;
                uint32_t bh[4][2];
#pragma unroll
                for (int n16 = 0; n16 < 2; n16++) {
                    const int row = wc * 32 + n16 * 16 + rowSel;
                    const uint32_t off = (uint32_t)(row * 64 + ((chunk ^ rmod) * 16));
                    uint32_t rh[4];
                    ldsm4(rh, sb + OFF_B + off);
                    bh[n16 * 2][0] = rh[0]; bh[n16 * 2 + 1][0] = rh[1];
                    bh[n16 * 2][1] = rh[2]; bh[n16 * 2 + 1][1] = rh[3];
                }
#pragma unroll
                for (int mt = 0; mt < 4; mt++) {
                    const int row = wr * 64 + mt * 16 + rowSel;
                    const uint32_t off = (uint32_t)(row * 64 + ((chunk ^ rmod) * 16));
                    uint32_t ah[4];
                    ldsm4(ah, sb + OFF_A + off);
#pragma unroll
                    for (int nt = 0; nt < 4; nt++) mma16816(acc[mt][nt], ah, bh[nt]);
                }
            }
        }
    }
};

// ---- merged pre/Q/K/V GEMM ------------------------------------------------
__global__ __launch_bounds__(256) void hmma_qkv(
    const __half* __restrict__ x16,
    const __half* wpre, const __half* wq, const __half* wk, const __half* wv,
    const float* __restrict__ bpre,
    __half* pre, __half* q16, __half* k16, __half* v16)
{
    extern __shared__ char smem_raw[];
    GemmCore gc_;
    gc_.init(smem_to_u32(smem_raw), threadIdx.x);

    const int g    = blockIdx.x >> 3;
    const int col0 = (blockIdx.x & 7) * 128;
    const int row0 = blockIdx.y * 128;

    const __half* Bp[4] = {wpre, wq, wk, wv};
    __half* Op[4] = {pre, q16, k16, v16};

    float acc[4][4][4];
    gc_.run(x16, Bp[g], row0, col0, acc);

    const int r0g = row0 + gc_.wr * 64 + (gc_.lane >> 2);
    const int c0g = col0 + gc_.wc * 32 + (gc_.lane & 3) * 2;
#pragma unroll
    for (int mt = 0; mt < 4; mt++) {
#pragma unroll
        for (int nt = 0; nt < 4; nt++) {
            const int gcc = c0g + nt * 8;
#pragma unroll
            for (int half = 0; half < 2; half++) {
                const int gr = r0g + mt * 16 + half * 8;
                float v0 = acc[mt][nt][half * 2 + 0];
                float v1 = acc[mt][nt][half * 2 + 1];
                if (g == 0) {
                    v0 += bpre[gcc]; v1 += bpre[gcc + 1];
                    v0 = v0 / (1.0f + __expf(-v0));
                    v1 = v1 / (1.0f + __expf(-v1));
                    *(__half2*)(Op[0] + (size_t)gr * CC + gcc) =
                        __floats2half2_rn(v0, v1);
                } else {
                    const int b = gr >> 10, n = gr & (NN - 1);
                    const int h = gcc >> 6, dh = gcc & 63;
                    const size_t o = ((size_t)(b * HH + h) * NN + n) * DH + dh;
                    *(__half2*)(Op[g] + o) = __floats2half2_rn(v0, v1);
                }
            }
        }
    }
}

// ---- logits (symmetric, upper-tri tiles) + proj/resid GEMM ----------------
__global__ __launch_bounds__(256) void hmma_gemm(
    const __half* __restrict__ As, const __half* __restrict__ Bs,
    const float* __restrict__ bias, const float* __restrict__ resid,
    float* __restrict__ outF, int mode, long long bsA, long long bsB)
{
    extern __shared__ char smem_raw[];
    GemmCore gc_;
    gc_.init(smem_to_u32(smem_raw), threadIdx.x);

    int row0, col0, ti = 0, tj = 0;
    if (mode == EPI_LOGITS) {
        int li = blockIdx.x, rem = 8;
        while (li >= rem) { li -= rem; rem--; ti++; }
        tj = ti + li;
        row0 = ti * 128; col0 = tj * 128;
    } else {
        row0 = blockIdx.y * 128;
        col0 = blockIdx.x * 128;
    }
    const int z = blockIdx.z;
    const __half* Ab = As + (size_t)z * bsA;
    const __half* Bb = Bs + (size_t)z * bsB;

    float acc[4][4][4];
    gc_.run(Ab, Bb, row0, col0, acc);

    const int r0g = row0 + gc_.wr * 64 + (gc_.lane >> 2);
    const int c0g = col0 + gc_.wc * 32 + (gc_.lane & 3) * 2;
#pragma unroll
    for (int mt = 0; mt < 4; mt++) {
#pragma unroll
        for (int nt = 0; nt < 4; nt++) {
            const int gcc = c0g + nt * 8;
#pragma unroll
            for (int half = 0; half < 2; half++) {
                const int gr = r0g + mt * 16 + half * 8;
                float v0 = acc[mt][nt][half * 2 + 0];
                float v1 = acc[mt][nt][half * 2 + 1];
                if (mode == EPI_LOGITS) {
                    float* base = outF + (size_t)z * NN * NN;
                    v0 *= 0.03125f; v1 *= 0.03125f;
                    base[(size_t)gr * NN + gcc]     = v0;
                    base[(size_t)gr * NN + gcc + 1] = v1;
                    if (ti != tj) {
                        base[(size_t)gcc * NN + gr]       = v0;
                        base[(size_t)(gcc + 1) * NN + gr] = v1;
                    }
                } else { // EPI_RESID
                    const size_t ro = (size_t)gr * CC + gcc;
                    outF[ro]     = v0 + bias[gcc]     + resid[ro];
                    outF[ro + 1] = v1 + bias[gcc + 1] + resid[ro + 1];
                }
            }
        }
    }
}

// ======================= HMMA flash attention (128-q tile) =================
// All single fp16: Q resident 16KB + double-buffered K/V (2 x 16KB) = 48KB.
#define SMQ 0
#define KVBASE 16384
#define KVST 16384
#define KV_K 0
#define KV_V 8192
#define SMEM_FATT (KVBASE + 2 * KVST)    // 49152

__global__ __launch_bounds__(256, 2) void fattn(
    const __half* __restrict__ q16, const __half* __restrict__ k16,
    const __half* __restrict__ v16,
    const float* __restrict__ logits, const float* __restrict__ pi_p,
    __half* __restrict__ ctx)
{
    extern __shared__ char sm[];
    const uint32_t sb = smem_to_u32(sm);
    const int t = threadIdx.x, lane = t & 31, w = t >> 5;
    const int bh = blockIdx.y, b = bh >> 4, h = bh & 15;
    const int q0 = blockIdx.x * 128;
    const size_t hoff = (size_t)bh * NN * DH;
    const float pi = pi_p[0];

    // Q async load (once)
#pragma unroll
    for (int i = 0; i < 4; i++) {
        const int id = t + i * 256;
        const int r = id >> 3, c = id & 7;
        const uint32_t off = (uint32_t)(r * 128 + ((c ^ (r & 7)) * 16));
        CP_ASYNC16(sb + SMQ + off, q16 + hoff + (size_t)(q0 + r) * DH + c * 8);
    }
    CP_COMMIT();

    auto load_kv = [&](int kt, int buf) {
        const uint32_t kvb = sb + KVBASE + buf * KVST;
#pragma unroll
        for (int i = 0; i < 2; i++) {
            const int id = t + i * 256;
            const int r = id >> 3, c = id & 7;
            const uint32_t off = (uint32_t)(r * 128 + ((c ^ (r & 7)) * 16));
            const size_t g = hoff + (size_t)(kt * 64 + r) * DH + c * 8;
            CP_ASYNC16(kvb + KV_K + off, k16 + g);
            CP_ASYNC16(kvb + KV_V + off, v16 + g);
        }
    };

    load_kv(0, 0);
    CP_COMMIT();

    float S[8][4], O[8][4];
#pragma unroll
    for (int j = 0; j < 8; j++)
#pragma unroll
        for (int c = 0; c < 4; c++) O[j][c] = 0.0f;
    float m0 = -1e30f, m1 = -1e30f, l0 = 0.0f, l1 = 0.0f;

    const int qr = w * 16 + (lane >> 2);
    const float* lgr = logits + (size_t)b * NN * NN + (size_t)(q0 + qr) * NN;
    const int rowSel = lane & 15, hiH = lane >> 4;

    for (int kt = 0; kt < 16; kt++) {
        const int mk = kt * 64;
        CP_WAIT0();
        __syncthreads();
        if (kt < 15) { load_kv(kt + 1, (kt + 1) & 1); CP_COMMIT(); }

        const uint32_t kvb = sb + KVBASE + (kt & 1) * KVST;

        // ---- S = Q K^T (1 term) ----
#pragma unroll
        for (int j = 0; j < 8; j++)
#pragma unroll
            for (int c = 0; c < 4; c++) S[j][c] = 0.0f;

#pragma unroll
        for (int kc = 0; kc < 4; kc++) {
            const int chunk = 2 * kc + hiH;
            uint32_t aq[4];
            {
                const int row = w * 16 + rowSel;
                const uint32_t off = (uint32_t)(row * 128 + ((chunk ^ (row & 7)) * 16));
                ldsm4(aq, sb + SMQ + off);
            }
#pragma unroll
            for (int j16 = 0; j16 < 4; j16++) {
                const int row = j16 * 16 + rowSel;
                const uint32_t off = (uint32_t)(row * 128 + ((chunk ^ (row & 7)) * 16));
                uint32_t rh[4];
                ldsm4(rh, kvb + KV_K + off);
                uint32_t b0[2] = {rh[0], rh[2]}, b1[2] = {rh[1], rh[3]};
                mma16816(S[2 * j16],     aq, b0);
                mma16816(S[2 * j16 + 1], aq, b1);
            }
        }

        // ---- bias + online softmax ----
        float mx0 = -1e30f, mx1 = -1e30f;
#pragma unroll
        for (int j = 0; j < 8; j++) {
            const float2 L0 = *(const float2*)(lgr + mk + j * 8 + (lane & 3) * 2);
            const float2 L1 = *(const float2*)(lgr + 8 * NN + mk + j * 8 + (lane & 3) * 2);
            S[j][0] = S[j][0] * 0.125f + pi * L0.x;
            S[j][1] = S[j][1] * 0.125f + pi * L0.y;
            S[j][2] = S[j][2] * 0.125f + pi * L1.x;
            S[j][3] = S[j][3] * 0.125f + pi * L1.y;
            mx0 = fmaxf(mx0, fmaxf(S[j][0], S[j][1]));
            mx1 = fmaxf(mx1, fmaxf(S[j][2], S[j][3]));
        }
        mx0 = fmaxf(mx0, __shfl_xor_sync(0xffffffffu, mx0, 1));
        mx0 = fmaxf(mx0, __shfl_xor_sync(0xffffffffu, mx0, 2));
        mx1 = fmaxf(mx1, __shfl_xor_sync(0xffffffffu, mx1, 1));
        mx1 = fmaxf(mx1, __shfl_xor_sync(0xffffffffu, mx1, 2));
        const float mn0 = fmaxf(m0, mx0), mn1 = fmaxf(m1, mx1);
        const float a0 = __expf(m0 - mn0), a1 = __expf(m1 - mn1);
        m0 = mn0; m1 = mn1;
        float s0 = 0.0f, s1 = 0.0f;
#pragma unroll
        for (int j = 0; j < 8; j++) {
            S[j][0] = __expf(S[j][0] - mn0); S[j][1] = __expf(S[j][1] - mn0);
            S[j][2] = __expf(S[j][2] - mn1); S[j][3] = __expf(S[j][3] - mn1);
            s0 += S[j][0] + S[j][1];
            s1 += S[j][2] + S[j][3];
        }
        s0 += __shfl_xor_sync(0xffffffffu, s0, 1);
        s0 += __shfl_xor_sync(0xffffffffu, s0, 2);
        s1 += __shfl_xor_sync(0xffffffffu, s1, 1);
        s1 += __shfl_xor_sync(0xffffffffu, s1, 2);
        l0 = l0 * a0 + s0; l1 = l1 * a1 + s1;
#pragma unroll
        for (int j = 0; j < 8; j++) {
            O[j][0] *= a0; O[j][1] *= a0; O[j][2] *= a1; O[j][3] *= a1;
        }

        // ---- O += P V (1 term) ----
#pragma unroll
        for (int kc = 0; kc < 4; kc++) {
            uint32_t ph[4];
#pragma unroll
            for (int half = 0; half < 2; half++) {
                const int j = 2 * kc + half;
                ph[half * 2 + 0] = pack_h2(S[j][0], S[j][1]);
                ph[half * 2 + 1] = pack_h2(S[j][2], S[j][3]);
            }
#pragma unroll
            for (int jc = 0; jc < 4; jc++) {
                const int row = kc * 16 + rowSel;
                const int chunk = 2 * jc + hiH;
                const uint32_t off = (uint32_t)(row * 128 + ((chunk ^ (row & 7)) * 16));
                uint32_t rv[4];
                ldsm4t(rv, kvb + KV_V + off);
                uint32_t v0[2] = {rv[0], rv[1]}, v1[2] = {rv[2], rv[3]};
                mma16816(O[2 * jc],     ph, v0);
                mma16816(O[2 * jc + 1], ph, v1);
            }
        }
    }

    // ---- epilogue: normalize, write ctx [B,N,C] fp16 ----
    const float inv0 = 1.0f / l0, inv1 = 1.0f / l1;
    const size_t r0o = (size_t)(b * NN + q0 + qr) * CC;
    const size_t r1o = r0o + (size_t)8 * CC;
    const int cb = h * DH + (lane & 3) * 2;
#pragma unroll
    for (int dj = 0; dj < 8; dj++) {
        const int col = cb + dj * 8;
        *(__half2*)(ctx + r0o + col) = __floats2half2_rn(O[dj][0] * inv0, O[dj][1] * inv0);
        *(__half2*)(ctx + r1o + col) = __floats2half2_rn(O[dj][2] * inv1, O[dj][3] * inv1);
    }
}

// ---------------------------------------------------------------------------
extern "C" void kernel_launch(void* const* d_in, const int* in_sizes, int n_in,
                              void* d_out, int out_size)
{
    (void)in_sizes; (void)n_in; (void)out_size;
    const float* x     = (const float*)d_in[0];
    const float* Wq    = (const float*)d_in[1];
    const float* Wk    = (const float*)d_in[2];
    const float* Wv    = (const float*)d_in[3];
    const float* Wproj = (const float*)d_in[4];
    const float* bproj = (const float*)d_in[5];
    const float* Wpre  = (const float*)d_in[6];
    const float* bpre  = (const float*)d_in[7];
    const float* pi    = (const float*)d_in[8];
    float* out = (float*)d_out;

    float* lgp;
    __half *x16, *pre, *ctx, *q16, *k16, *v16;
    __half *wpre, *wq, *wk, *wv, *wp;
    cudaGetSymbolAddress((void**)&lgp,  g_logits);
    cudaGetSymbolAddress((void**)&x16,  g_x16);
    cudaGetSymbolAddress((void**)&pre,  g_pre);
    cudaGetSymbolAddress((void**)&ctx,  g_ctx);
    cudaGetSymbolAddress((void**)&q16,  g_q16);
    cudaGetSymbolAddress((void**)&k16,  g_k16);
    cudaGetSymbolAddress((void**)&v16,  g_v16);
    cudaGetSymbolAddress((void**)&wpre, g_wpre);
    cudaGetSymbolAddress((void**)&wq,   g_wq);
    cudaGetSymbolAddress((void**)&wk,   g_wk);
    cudaGetSymbolAddress((void**)&wv,   g_wv);
    cudaGetSymbolAddress((void**)&wp,   g_wp);

    cudaFuncSetAttribute(hmma_qkv,  cudaFuncAttributeMaxDynamicSharedMemorySize, SMEM_HMMA);
    cudaFuncSetAttribute(hmma_gemm, cudaFuncAttributeMaxDynamicSharedMemorySize, SMEM_HMMA);
    cudaFuncSetAttribute(fattn,     cudaFuncAttributeMaxDynamicSharedMemorySize, SMEM_FATT);

    // ---- prep ----
    dim3 wst(32, 8), wsg(32, 32, 5);
    wround_T5<<<wsg, wst>>>(Wpre, Wq, Wk, Wv, Wproj, wpre, wq, wk, wv, wp);
    const int n2 = MROWS * CC / 2;
    round2h<<<(n2 + 255) / 256, 256>>>((const float2*)x, (__half2*)x16, n2);

    // ---- merged pre/Q/K/V GEMM ----
    dim3 mb(256);
    dim3 gqkv(32, MROWS / 128, 1);
    hmma_qkv<<<gqkv, mb, SMEM_HMMA>>>(x16, wpre, wq, wk, wv, bpre,
                                      pre, q16, k16, v16);

    // ---- logits GEMM (symmetric: 36 upper-tri tiles/batch) ----
    dim3 glog(36, 1, BB);
    hmma_gemm<<<glog, mb, SMEM_HMMA>>>(pre, pre, nullptr, nullptr,
                                       lgp, EPI_LOGITS,
                                       (long long)NN * CC, (long long)NN * CC);

    // ---- HMMA flash attention ----
    dim3 ga(NN / 128, BB * HH);
    fattn<<<ga, 256, SMEM_FATT>>>(q16, k16, v16, lgp, pi, ctx);

    // ---- projection + residual ----
    dim3 gl(CC / 128, MROWS / 128, 1);
    hmma_gemm<<<gl, mb, SMEM_HMMA>>>(ctx, wp, bproj, x,
                                     out, EPI_RESID, 0, 0);
}